// round 6
// baseline (speedup 1.0000x reference)
#include <cuda_runtime.h>
#include <cstdint>

#define B_   4
#define S_   1024
#define D_   2048
#define H_   32
#define KVH_ 8
#define HD_  64

#define STAGES 3

// ---------------- device scratch ----------------
__device__ float g_q[B_ * S_ * H_ * HD_];
__device__ float g_k[B_ * S_ * KVH_ * HD_];
__device__ float g_v[B_ * S_ * KVH_ * HD_];
__device__ float g_attn[B_ * S_ * H_ * HD_];
__device__ float g_xr[B_ * S_ * D_];
__device__ float g_Wqr[2048 * 2048];
__device__ float g_Wkr[2048 * 512];
__device__ float g_Wvr[2048 * 512];
__device__ float g_Wor[2048 * 2048];

__device__ __forceinline__ float tf32r(float x) {
    float r; asm("cvt.rna.tf32.f32 %0, %1;" : "=f"(r) : "f"(x)); return r;
}
__device__ __forceinline__ float4 tf32r4(float4 v) {
    v.x = tf32r(v.x); v.y = tf32r(v.y); v.z = tf32r(v.z); v.w = tf32r(v.w);
    return v;
}
__device__ __forceinline__ uint32_t smem_u32(const void* p) {
    uint32_t a;
    asm("{ .reg .u64 t; cvta.to.shared.u64 t, %1; cvt.u32.u64 %0, t; }"
        : "=r"(a) : "l"(p));
    return a;
}
__device__ __forceinline__ void cpa16(uint32_t dst, const void* src) {
    asm volatile("cp.async.cg.shared.global [%0], [%1], 16;" :: "r"(dst), "l"(src));
}
#define CP_COMMIT() asm volatile("cp.async.commit_group;" ::: "memory")
#define CP_WAIT(n)  asm volatile("cp.async.wait_group %0;" :: "n"(n) : "memory")

__device__ __forceinline__ void mma_tf32(float* d, const uint32_t* a, const uint32_t* b) {
    asm volatile(
        "mma.sync.aligned.m16n8k8.row.col.f32.tf32.tf32.f32 "
        "{%0,%1,%2,%3}, {%4,%5,%6,%7}, {%8,%9}, {%0,%1,%2,%3};"
        : "+f"(d[0]), "+f"(d[1]), "+f"(d[2]), "+f"(d[3])
        : "r"(a[0]), "r"(a[1]), "r"(a[2]), "r"(a[3]), "r"(b[0]), "r"(b[1]));
}
__device__ __forceinline__ void mma_tf32f(float* d, const float* a, const float* b) {
    asm volatile(
        "mma.sync.aligned.m16n8k8.row.col.f32.tf32.tf32.f32 "
        "{%0,%1,%2,%3}, {%4,%5,%6,%7}, {%8,%9}, {%0,%1,%2,%3};"
        : "+f"(d[0]), "+f"(d[1]), "+f"(d[2]), "+f"(d[3])
        : "r"(__float_as_uint(a[0])), "r"(__float_as_uint(a[1])),
          "r"(__float_as_uint(a[2])), "r"(__float_as_uint(a[3])),
          "r"(__float_as_uint(b[0])), "r"(__float_as_uint(b[1])));
}

// ---------------------------------------------------------------------------
__global__ void round_kernel(const float* __restrict__ src,
                             float* __restrict__ dst, int n4)
{
    int i = blockIdx.x * blockDim.x + threadIdx.x;
    if (i < n4)
        *(float4*)(dst + i * 4) = tf32r4(*(const float4*)(src + i * 4));
}

// ---------------------------------------------------------------------------
// tf32 mma.sync GEMM, cp.async 3-stage. CTA = 128x128 tile, 4 warps of 64x64.
// ---------------------------------------------------------------------------
#define ASTG 2560   // 128 * 20 floats
#define BSTG 2176   // 16 * 136 floats

__device__ __forceinline__ void gemm128_cp(
    const float* __restrict__ A, const float* __restrict__ W,
    float* __restrict__ C, int ldw, int ldc, int row0, int wc0)
{
    extern __shared__ __align__(16) float sm[];
    float* As = sm;                       // [STAGES][128][20]
    float* Bs = sm + STAGES * ASTG;       // [STAGES][16][136]
    const uint32_t asb = smem_u32(As), bsb = smem_u32(Bs);

    const int tid  = threadIdx.x;         // 128
    const int wid  = tid >> 5, lane = tid & 31;
    const int g    = lane >> 2, c = lane & 3;
    const int wm   = (wid & 1) * 64;
    const int wn   = (wid >> 1) * 64;

    // cp.async mapping: A row = tid (16 floats), B row = tid>>3, col = (tid&7)*16
    const float* asrc = A + (size_t)(row0 + tid) * 2048;
    const int bk = tid >> 3, bn = (tid & 7) * 16;
    const float* bsrc = W + (size_t)bk * ldw + wc0 + bn;
    const uint32_t adst = asb + (tid * 20) * 4;
    const uint32_t bdst = bsb + (bk * 136 + bn) * 4;

    float acc[4][8][4];
    #pragma unroll
    for (int mt = 0; mt < 4; mt++)
        #pragma unroll
        for (int nt = 0; nt < 8; nt++)
            #pragma unroll
            for (int e = 0; e < 4; e++) acc[mt][nt][e] = 0.f;

    #pragma unroll
    for (int s = 0; s < STAGES - 1; s++) {
        const float* ap = asrc + s * 16;
        #pragma unroll
        for (int q = 0; q < 4; q++)
            cpa16(adst + s * ASTG * 4 + q * 16, ap + q * 4);
        const float* bp = bsrc + (size_t)s * 16 * ldw;
        #pragma unroll
        for (int q = 0; q < 4; q++)
            cpa16(bdst + s * BSTG * 4 + q * 16, bp + q * 4);
        CP_COMMIT();
    }

    int buf = 0;
    for (int i = 0; i < 128; ++i) {
        CP_WAIT(STAGES - 2);
        __syncthreads();

        const float* Ab = As + buf * ASTG;
        const float* Bb = Bs + buf * BSTG;
        #pragma unroll
        for (int ks = 0; ks < 16; ks += 8) {
            uint32_t af[4][4];
            #pragma unroll
            for (int mt = 0; mt < 4; mt++) {
                const float* ap = &Ab[(wm + mt * 16 + g) * 20 + ks + c];
                af[mt][0] = __float_as_uint(ap[0]);
                af[mt][1] = __float_as_uint(ap[8 * 20]);
                af[mt][2] = __float_as_uint(ap[4]);
                af[mt][3] = __float_as_uint(ap[8 * 20 + 4]);
            }
            uint32_t bfr[8][2];
            #pragma unroll
            for (int nt = 0; nt < 8; nt++) {
                bfr[nt][0] = __float_as_uint(Bb[(ks + c) * 136     + wn + nt * 8 + g]);
                bfr[nt][1] = __float_as_uint(Bb[(ks + c + 4) * 136 + wn + nt * 8 + g]);
            }
            #pragma unroll
            for (int mt = 0; mt < 4; mt++)
                #pragma unroll
                for (int nt = 0; nt < 8; nt++)
                    mma_tf32(acc[mt][nt], af[mt], bfr[nt]);
        }

        int nk = i + STAGES - 1;
        if (nk < 128) {
            int s = nk % STAGES;
            const float* ap = asrc + nk * 16;
            #pragma unroll
            for (int q = 0; q < 4; q++)
                cpa16(adst + s * ASTG * 4 + q * 16, ap + q * 4);
            const float* bp = bsrc + (size_t)nk * 16 * ldw;
            #pragma unroll
            for (int q = 0; q < 4; q++)
                cpa16(bdst + s * BSTG * 4 + q * 16, bp + q * 4);
        }
        CP_COMMIT();
        buf = buf + 1 == STAGES ? 0 : buf + 1;
    }

    #pragma unroll
    for (int mt = 0; mt < 4; mt++) {
        int r = row0 + wm + mt * 16 + g;
        #pragma unroll
        for (int nt = 0; nt < 8; nt++) {
            int col = wc0 + wn + nt * 8 + 2 * c;
            *(float2*)&C[(size_t)r * ldc + col]       = make_float2(acc[mt][nt][0], acc[mt][nt][1]);
            *(float2*)&C[(size_t)(r + 8) * ldc + col] = make_float2(acc[mt][nt][2], acc[mt][nt][3]);
        }
    }
}

__global__ __launch_bounds__(128) void qkv_gemm_tc(const float* __restrict__ X)
{
    int col0 = blockIdx.x * 128, row0 = blockIdx.y * 128;
    const float* W; float* C; int ldw, ldc, wc0;
    if (col0 < 2048)      { W = g_Wqr; C = g_q; ldw = 2048; ldc = 2048; wc0 = col0; }
    else if (col0 < 2560) { W = g_Wkr; C = g_k; ldw = 512;  ldc = 512;  wc0 = col0 - 2048; }
    else                  { W = g_Wvr; C = g_v; ldw = 512;  ldc = 512;  wc0 = col0 - 2560; }
    gemm128_cp(X, W, C, ldw, ldc, row0, wc0);
}

__global__ __launch_bounds__(128) void out_gemm_tc(float* __restrict__ out)
{
    int col0 = blockIdx.x * 128, row0 = blockIdx.y * 128;
    gemm128_cp(g_attn, g_Wor, out, 2048, 2048, row0, col0);
}

// ---------------------------------------------------------------------------
__global__ void rope_kernel(const float* __restrict__ cosb,
                            const float* __restrict__ sinb, int which)
{
    float* buf = which ? g_k : g_q;
    int nh = which ? KVH_ : H_;
    int idx = blockIdx.x * blockDim.x + threadIdx.x;
    int total = B_ * S_ * nh * 32;
    if (idx >= total) return;
    int d = idx & 31;
    int h = (idx >> 5) % nh;
    int s = (idx / (32 * nh)) % S_;
    int b = idx / (32 * nh * S_);
    float* row = buf + (((size_t)(b * S_ + s)) * nh + h) * 64;
    float c1 = cosb[s * 64 + d],      s1 = sinb[s * 64 + d];
    float c2 = cosb[s * 64 + d + 32], s2 = sinb[s * 64 + d + 32];
    float x1 = row[d], x2 = row[d + 32];
    row[d]      = x1 * c1 - x2 * s1;
    row[d + 32] = x2 * c2 + x1 * s2;
}

// ---------------------------------------------------------------------------
// Flash attention, tf32 mma.sync + register prefetch (unchanged from R5)
// ---------------------------------------------------------------------------
__global__ __launch_bounds__(256) void flash_mma_kernel()
{
    __shared__ __align__(16) float sK[64][68];
    __shared__ __align__(16) float sV[64][72];

    const int tid = threadIdx.x;
    const int wid = tid >> 5, lane = tid & 31;
    const int g = lane >> 2, c = lane & 3;
    const int qb = blockIdx.x, h = blockIdx.y, b = blockIdx.z;
    const int kvh = h >> 2;

    const float* qbase = g_q + ((size_t)(b * S_ + qb * 128 + wid * 16) * H_ + h) * 64;
    float qa[8][4];
    #pragma unroll
    for (int kc = 0; kc < 8; kc++) {
        qa[kc][0] = tf32r(qbase[(size_t)g * 2048       + kc * 8 + c]     * 0.125f);
        qa[kc][1] = tf32r(qbase[(size_t)(g + 8) * 2048 + kc * 8 + c]     * 0.125f);
        qa[kc][2] = tf32r(qbase[(size_t)g * 2048       + kc * 8 + c + 4] * 0.125f);
        qa[kc][3] = tf32r(qbase[(size_t)(g + 8) * 2048 + kc * 8 + c + 4] * 0.125f);
    }

    float o[8][4];
    #pragma unroll
    for (int dt = 0; dt < 8; dt++)
        #pragma unroll
        for (int e = 0; e < 4; e++) o[dt][e] = 0.f;
    float m0 = -1.0e30f, m1 = -1.0e30f, l0 = 0.f, l1 = 0.f;

    const float* kvK = g_k + ((size_t)(b * S_) * KVH_ + kvh) * 64;
    const float* kvV = g_v + ((size_t)(b * S_) * KVH_ + kvh) * 64;

    float4 kr[4], vr[4];
    #pragma unroll
    for (int u = 0; u < 4; u++) {
        int idx = tid + u * 256;
        int r = idx >> 4, c4 = idx & 15;
        kr[u] = *(const float4*)(kvK + (size_t)r * 512 + c4 * 4);
        vr[u] = *(const float4*)(kvV + (size_t)r * 512 + c4 * 4);
    }

    for (int jt = 0; jt < 16; ++jt) {
        __syncthreads();
        #pragma unroll
        for (int u = 0; u < 4; u++) {
            int idx = tid + u * 256;
            int r = idx >> 4, c4 = idx & 15;
            *(float4*)&sK[r][c4 * 4] = tf32r4(kr[u]);
            *(float4*)&sV[r][c4 * 4] = tf32r4(vr[u]);
        }
        __syncthreads();

        if (jt < 15) {
            const float* kn = kvK + (size_t)(jt + 1) * 64 * 512;
            const float* vn = kvV + (size_t)(jt + 1) * 64 * 512;
            #pragma unroll
            for (int u = 0; u < 4; u++) {
                int idx = tid + u * 256;
                int r = idx >> 4, c4 = idx & 15;
                kr[u] = *(const float4*)(kn + (size_t)r * 512 + c4 * 4);
                vr[u] = *(const float4*)(vn + (size_t)r * 512 + c4 * 4);
            }
        }

        float s[8][4];
        #pragma unroll
        for (int nt = 0; nt < 8; nt++)
            #pragma unroll
            for (int e = 0; e < 4; e++) s[nt][e] = 0.f;
        #pragma unroll
        for (int nt = 0; nt < 8; nt++) {
            #pragma unroll
            for (int kc = 0; kc < 8; kc++) {
                float bf[2];
                bf[0] = sK[nt * 8 + g][kc * 8 + c];
                bf[1] = sK[nt * 8 + g][kc * 8 + c + 4];
                mma_tf32f(s[nt], qa[kc], bf);
            }
        }

        float tm0 = -1.0e30f, tm1 = -1.0e30f;
        #pragma unroll
        for (int nt = 0; nt < 8; nt++) {
            tm0 = fmaxf(tm0, fmaxf(s[nt][0], s[nt][1]));
            tm1 = fmaxf(tm1, fmaxf(s[nt][2], s[nt][3]));
        }
        tm0 = fmaxf(tm0, __shfl_xor_sync(0xffffffffu, tm0, 1));
        tm0 = fmaxf(tm0, __shfl_xor_sync(0xffffffffu, tm0, 2));
        tm1 = fmaxf(tm1, __shfl_xor_sync(0xffffffffu, tm1, 1));
        tm1 = fmaxf(tm1, __shfl_xor_sync(0xffffffffu, tm1, 2));

        float nm0 = fmaxf(m0, tm0), nm1 = fmaxf(m1, tm1);
        float al0 = __expf(m0 - nm0), al1 = __expf(m1 - nm1);
        m0 = nm0; m1 = nm1;

        float sum0 = 0.f, sum1 = 0.f;
        #pragma unroll
        for (int nt = 0; nt < 8; nt++) {
            s[nt][0] = tf32r(__expf(s[nt][0] - nm0));
            s[nt][1] = tf32r(__expf(s[nt][1] - nm0));
            s[nt][2] = tf32r(__expf(s[nt][2] - nm1));
            s[nt][3] = tf32r(__expf(s[nt][3] - nm1));
            sum0 += s[nt][0] + s[nt][1];
            sum1 += s[nt][2] + s[nt][3];
        }
        sum0 += __shfl_xor_sync(0xffffffffu, sum0, 1);
        sum0 += __shfl_xor_sync(0xffffffffu, sum0, 2);
        sum1 += __shfl_xor_sync(0xffffffffu, sum1, 1);
        sum1 += __shfl_xor_sync(0xffffffffu, sum1, 2);
        l0 = l0 * al0 + sum0;
        l1 = l1 * al1 + sum1;

        #pragma unroll
        for (int dt = 0; dt < 8; dt++) {
            o[dt][0] *= al0; o[dt][1] *= al0;
            o[dt][2] *= al1; o[dt][3] *= al1;
        }

        const int qbase_l = lane & ~3;
        const int src0 = qbase_l + (c >> 1);
        const int src1 = src0 + 2;
        const int e = c & 1;
        #pragma unroll
        for (int kc = 0; kc < 8; kc++) {
            float t00 = __shfl_sync(0xffffffffu, s[kc][0], src0);
            float t01 = __shfl_sync(0xffffffffu, s[kc][1], src0);
            float t02 = __shfl_sync(0xffffffffu, s[kc][2], src0);
            float t03 = __shfl_sync(0xffffffffu, s[kc][3], src0);
            float t10 = __shfl_sync(0xffffffffu, s[kc][0], src1);
            float t11 = __shfl_sync(0xffffffffu, s[kc][1], src1);
            float t12 = __shfl_sync(0xffffffffu, s[kc][2], src1);
            float t13 = __shfl_sync(0xffffffffu, s[kc][3], src1);
            float a[4];
            a[0] = e ? t01 : t00;
            a[1] = e ? t03 : t02;
            a[2] = e ? t11 : t10;
            a[3] = e ? t13 : t12;
            #pragma unroll
            for (int dt = 0; dt < 8; dt++) {
                float bf[2];
                bf[0] = sV[kc * 8 + c][dt * 8 + g];
                bf[1] = sV[kc * 8 + c + 4][dt * 8 + g];
                mma_tf32f(o[dt], a, bf);
            }
        }
    }

    float inv0 = 1.f / l0, inv1 = 1.f / l1;
    float* obase = g_attn + ((size_t)(b * S_ + qb * 128 + wid * 16) * H_ + h) * 64;
    #pragma unroll
    for (int dt = 0; dt < 8; dt++) {
        *(float2*)&obase[(size_t)g * 2048 + dt * 8 + 2 * c] =
            make_float2(tf32r(o[dt][0] * inv0), tf32r(o[dt][1] * inv0));
        *(float2*)&obase[(size_t)(g + 8) * 2048 + dt * 8 + 2 * c] =
            make_float2(tf32r(o[dt][2] * inv1), tf32r(o[dt][3] * inv1));
    }
}

// ---------------------------------------------------------------------------
extern "C" void kernel_launch(void* const* d_in, const int* in_sizes, int n_in,
                              void* d_out, int out_size)
{
    (void)in_sizes; (void)n_in; (void)out_size;
    const float* x   = (const float*)d_in[0];
    const float* cb  = (const float*)d_in[1];
    const float* sb  = (const float*)d_in[2];
    const float* Wq  = (const float*)d_in[3];
    const float* Wk  = (const float*)d_in[4];
    const float* Wv  = (const float*)d_in[5];
    const float* Wo  = (const float*)d_in[6];
    float* out = (float*)d_out;

    const int GEMM_SMEM = STAGES * (ASTG + BSTG) * 4;   // 56832 B
    cudaFuncSetAttribute(qkv_gemm_tc, cudaFuncAttributeMaxDynamicSharedMemorySize, GEMM_SMEM);
    cudaFuncSetAttribute(out_gemm_tc, cudaFuncAttributeMaxDynamicSharedMemorySize, GEMM_SMEM);

    float* xr; float* wqr; float* wkr; float* wvr; float* wor;
    cudaGetSymbolAddress((void**)&xr,  g_xr);
    cudaGetSymbolAddress((void**)&wqr, g_Wqr);
    cudaGetSymbolAddress((void**)&wkr, g_Wkr);
    cudaGetSymbolAddress((void**)&wvr, g_Wvr);
    cudaGetSymbolAddress((void**)&wor, g_Wor);

    round_kernel<<<(8388608 / 4 + 255) / 256, 256>>>(x,  xr,  8388608 / 4);
    round_kernel<<<(4194304 / 4 + 255) / 256, 256>>>(Wq, wqr, 4194304 / 4);
    round_kernel<<<(1048576 / 4 + 255) / 256, 256>>>(Wk, wkr, 1048576 / 4);
    round_kernel<<<(1048576 / 4 + 255) / 256, 256>>>(Wv, wvr, 1048576 / 4);
    round_kernel<<<(4194304 / 4 + 255) / 256, 256>>>(Wo, wor, 4194304 / 4);

    qkv_gemm_tc<<<dim3(3072 / 128, 4096 / 128), 128, GEMM_SMEM>>>(xr);

    rope_kernel<<<(B_ * S_ * H_ * 32 + 255) / 256, 256>>>(cb, sb, 0);
    rope_kernel<<<(B_ * S_ * KVH_ * 32 + 255) / 256, 256>>>(cb, sb, 1);

    flash_mma_kernel<<<dim3(S_ / 128, H_, B_), 256>>>();

    out_gemm_tc<<<dim3(2048 / 128, 4096 / 128), 128, GEMM_SMEM>>>(out);
}

// round 7
// speedup vs baseline: 1.8339x; 1.8339x over previous
#include <cuda_runtime.h>
#include <cuda_fp16.h>
#include <cstdint>

#define B_   4
#define S_   1024
#define D_   2048
#define H_   32
#define KVH_ 8
#define HD_  64

#define STAGES 4
#define STG_H  3072   // halves per stage per matrix: 128 * 24

// ---------------- device scratch ----------------
__device__ float  g_q[B_ * S_ * H_ * HD_];
__device__ float  g_k[B_ * S_ * KVH_ * HD_];
__device__ float  g_v[B_ * S_ * KVH_ * HD_];
__device__ __half g_attnh[B_ * S_ * H_ * HD_];
__device__ __half g_xh[B_ * S_ * D_];
__device__ __half g_Wqh[2048 * 2048];   // transposed [N][K]
__device__ __half g_Wkh[512 * 2048];
__device__ __half g_Wvh[512 * 2048];
__device__ __half g_Woh[2048 * 2048];

__device__ __forceinline__ uint32_t smem_u32(const void* p) {
    uint32_t a;
    asm("{ .reg .u64 t; cvta.to.shared.u64 t, %1; cvt.u32.u64 %0, t; }"
        : "=r"(a) : "l"(p));
    return a;
}
__device__ __forceinline__ void cpa16(uint32_t dst, const void* src) {
    asm volatile("cp.async.cg.shared.global [%0], [%1], 16;" :: "r"(dst), "l"(src));
}
#define CP_COMMIT() asm volatile("cp.async.commit_group;" ::: "memory")
#define CP_WAIT(n)  asm volatile("cp.async.wait_group %0;" :: "n"(n) : "memory")

__device__ __forceinline__ uint32_t packh2(float a, float b) {
    __half2 h = __floats2half2_rn(a, b);
    return *(uint32_t*)&h;
}
__device__ __forceinline__ void mma_f16(float* d, const uint32_t* a, const uint32_t* b) {
    asm volatile(
        "mma.sync.aligned.m16n8k16.row.col.f32.f16.f16.f32 "
        "{%0,%1,%2,%3}, {%4,%5,%6,%7}, {%8,%9}, {%0,%1,%2,%3};"
        : "+f"(d[0]), "+f"(d[1]), "+f"(d[2]), "+f"(d[3])
        : "r"(a[0]), "r"(a[1]), "r"(a[2]), "r"(a[3]), "r"(b[0]), "r"(b[1]));
}

// ---------------------------------------------------------------------------
// f32 -> f16 straight conversion (float4 -> 4 halves)
// ---------------------------------------------------------------------------
__global__ void convh_kernel(const float* __restrict__ src,
                             __half* __restrict__ dst, int n4)
{
    int i = blockIdx.x * blockDim.x + threadIdx.x;
    if (i < n4) {
        float4 v = *(const float4*)(src + i * 4);
        uint2 u;
        u.x = packh2(v.x, v.y);
        u.y = packh2(v.z, v.w);
        *(uint2*)(dst + i * 4) = u;
    }
}

// f32 [rows][cols] -> f16 transposed [cols][rows]
__global__ void convT_kernel(const float* __restrict__ src,
                             __half* __restrict__ dst, int rows, int cols)
{
    __shared__ float t[32][33];
    int bx = blockIdx.x * 32, by = blockIdx.y * 32;
    int tx = threadIdx.x, ty = threadIdx.y;   // 32 x 8
    #pragma unroll
    for (int j = 0; j < 32; j += 8)
        t[ty + j][tx] = src[(size_t)(by + ty + j) * cols + bx + tx];
    __syncthreads();
    #pragma unroll
    for (int j = 0; j < 32; j += 8)
        dst[(size_t)(bx + ty + j) * rows + by + tx] = __float2half(t[tx][ty + j]);
}

// ---------------------------------------------------------------------------
// fp16 mma.sync GEMM, cp.async 4-stage. CTA 128x128, 8 warps of 64x32. K=2048.
// A [*,2048] half row-major. Wt [N][2048] half (transposed weight).
// ---------------------------------------------------------------------------
__device__ __forceinline__ void gemm128_h(
    const __half* __restrict__ A, const __half* __restrict__ Wt,
    float* __restrict__ C, int ldc, int row0, int wc0)
{
    extern __shared__ __align__(16) __half smh[];
    __half* As = smh;                      // [STAGES][128][24]
    __half* Bs = smh + STAGES * STG_H;     // [STAGES][128][24]  (n-major rows)
    const uint32_t asb = smem_u32(As), bsb = smem_u32(Bs);

    const int tid = threadIdx.x;           // 256
    const int wid = tid >> 5, lane = tid & 31;
    const int g = lane >> 2, c = lane & 3;
    const int wm = (wid & 1) * 64;
    const int wn = (wid >> 1) * 32;

    const int lrow = tid >> 1, seg = tid & 1;   // 128 rows x two 16B chunks
    const __half* asrc = A  + (size_t)(row0 + lrow) * 2048 + seg * 8;
    const __half* bsrc = Wt + (size_t)(wc0 + lrow) * 2048 + seg * 8;
    const uint32_t adst = asb + (lrow * 24 + seg * 8) * 2;
    const uint32_t bdst = bsb + (lrow * 24 + seg * 8) * 2;

    float acc[4][4][4];
    #pragma unroll
    for (int mt = 0; mt < 4; mt++)
        #pragma unroll
        for (int nt = 0; nt < 4; nt++)
            #pragma unroll
            for (int e = 0; e < 4; e++) acc[mt][nt][e] = 0.f;

    #pragma unroll
    for (int s = 0; s < STAGES - 1; s++) {
        cpa16(adst + s * STG_H * 2, asrc + s * 16);
        cpa16(bdst + s * STG_H * 2, bsrc + s * 16);
        CP_COMMIT();
    }

    int buf = 0;
    for (int i = 0; i < 128; ++i) {
        CP_WAIT(STAGES - 2);
        __syncthreads();

        const __half* Ab = As + buf * STG_H;
        const __half* Bb = Bs + buf * STG_H;
        uint32_t af[4][4], bf[4][2];
        #pragma unroll
        for (int mt = 0; mt < 4; mt++) {
            int m = wm + mt * 16 + g;
            af[mt][0] = *(const uint32_t*)(Ab + m * 24 + 2 * c);
            af[mt][1] = *(const uint32_t*)(Ab + (m + 8) * 24 + 2 * c);
            af[mt][2] = *(const uint32_t*)(Ab + m * 24 + 2 * c + 8);
            af[mt][3] = *(const uint32_t*)(Ab + (m + 8) * 24 + 2 * c + 8);
        }
        #pragma unroll
        for (int nt = 0; nt < 4; nt++) {
            int n = wn + nt * 8 + g;
            bf[nt][0] = *(const uint32_t*)(Bb + n * 24 + 2 * c);
            bf[nt][1] = *(const uint32_t*)(Bb + n * 24 + 2 * c + 8);
        }
        #pragma unroll
        for (int mt = 0; mt < 4; mt++)
            #pragma unroll
            for (int nt = 0; nt < 4; nt++)
                mma_f16(acc[mt][nt], af[mt], bf[nt]);

        int nk = i + STAGES - 1;
        if (nk < 128) {
            int s = nk & (STAGES - 1);
            cpa16(adst + s * STG_H * 2, asrc + nk * 16);
            cpa16(bdst + s * STG_H * 2, bsrc + nk * 16);
        }
        CP_COMMIT();
        buf = (buf + 1) & (STAGES - 1);
    }

    #pragma unroll
    for (int mt = 0; mt < 4; mt++) {
        int r = row0 + wm + mt * 16 + g;
        #pragma unroll
        for (int nt = 0; nt < 4; nt++) {
            int col = wc0 + wn + nt * 8 + 2 * c;
            *(float2*)&C[(size_t)r * ldc + col]       = make_float2(acc[mt][nt][0], acc[mt][nt][1]);
            *(float2*)&C[(size_t)(r + 8) * ldc + col] = make_float2(acc[mt][nt][2], acc[mt][nt][3]);
        }
    }
}

__global__ __launch_bounds__(256) void qkv_gemm_h()
{
    int col0 = blockIdx.x * 128, row0 = blockIdx.y * 128;
    const __half* Wt; float* C; int ldc, wc0;
    if (col0 < 2048)      { Wt = g_Wqh; C = g_q; ldc = 2048; wc0 = col0; }
    else if (col0 < 2560) { Wt = g_Wkh; C = g_k; ldc = 512;  wc0 = col0 - 2048; }
    else                  { Wt = g_Wvh; C = g_v; ldc = 512;  wc0 = col0 - 2560; }
    gemm128_h(g_xh, Wt, C, ldc, row0, wc0);
}

__global__ __launch_bounds__(256) void out_gemm_h(float* __restrict__ out)
{
    int col0 = blockIdx.x * 128, row0 = blockIdx.y * 128;
    gemm128_h(g_attnh, g_Woh, out, 2048, row0, col0);
}

// ---------------------------------------------------------------------------
__global__ void rope_kernel(const float* __restrict__ cosb,
                            const float* __restrict__ sinb, int which)
{
    float* buf = which ? g_k : g_q;
    int nh = which ? KVH_ : H_;
    int idx = blockIdx.x * blockDim.x + threadIdx.x;
    int total = B_ * S_ * nh * 32;
    if (idx >= total) return;
    int d = idx & 31;
    int h = (idx >> 5) % nh;
    int s = (idx / (32 * nh)) % S_;
    int b = idx / (32 * nh * S_);
    float* row = buf + (((size_t)(b * S_ + s)) * nh + h) * 64;
    float c1 = cosb[s * 64 + d],      s1 = sinb[s * 64 + d];
    float c2 = cosb[s * 64 + d + 32], s2 = sinb[s * 64 + d + 32];
    float x1 = row[d], x2 = row[d + 32];
    row[d]      = x1 * c1 - x2 * s1;
    row[d + 32] = x2 * c2 + x1 * s2;
}

// ---------------------------------------------------------------------------
// Flash attention, fp16 m16n8k16. Block = 128 q-rows x (head, batch).
// Warp w owns rows w*16..w*16+15. P stays in registers (native layout match).
// Output written as half to g_attnh.
// ---------------------------------------------------------------------------
__global__ __launch_bounds__(256) void flash_h_kernel()
{
    __shared__ __align__(16) __half sK[64][72];
    __shared__ __align__(16) __half sV[64][72];

    const int tid = threadIdx.x;
    const int wid = tid >> 5, lane = tid & 31;
    const int g = lane >> 2, c = lane & 3;
    const int qb = blockIdx.x, h = blockIdx.y, b = blockIdx.z;
    const int kvh = h >> 2;

    const float* qbase = g_q + ((size_t)(b * S_ + qb * 128 + wid * 16) * H_ + h) * 64;
    uint32_t qa[4][4];
    #pragma unroll
    for (int kc = 0; kc < 4; kc++) {
        float2 v;
        v = *(const float2*)&qbase[(size_t)g * 2048       + kc * 16 + 2 * c];
        qa[kc][0] = packh2(v.x * 0.125f, v.y * 0.125f);
        v = *(const float2*)&qbase[(size_t)(g + 8) * 2048 + kc * 16 + 2 * c];
        qa[kc][1] = packh2(v.x * 0.125f, v.y * 0.125f);
        v = *(const float2*)&qbase[(size_t)g * 2048       + kc * 16 + 8 + 2 * c];
        qa[kc][2] = packh2(v.x * 0.125f, v.y * 0.125f);
        v = *(const float2*)&qbase[(size_t)(g + 8) * 2048 + kc * 16 + 8 + 2 * c];
        qa[kc][3] = packh2(v.x * 0.125f, v.y * 0.125f);
    }

    float o[8][4];
    #pragma unroll
    for (int dt = 0; dt < 8; dt++)
        #pragma unroll
        for (int e = 0; e < 4; e++) o[dt][e] = 0.f;
    float m0 = -1.0e30f, m1 = -1.0e30f, l0 = 0.f, l1 = 0.f;

    const float* kvK = g_k + ((size_t)(b * S_) * KVH_ + kvh) * 64;
    const float* kvV = g_v + ((size_t)(b * S_) * KVH_ + kvh) * 64;

    float4 kr[4], vr[4];
    #pragma unroll
    for (int u = 0; u < 4; u++) {
        int idx = tid + u * 256;
        int r = idx >> 4, c4 = idx & 15;
        kr[u] = *(const float4*)(kvK + (size_t)r * 512 + c4 * 4);
        vr[u] = *(const float4*)(kvV + (size_t)r * 512 + c4 * 4);
    }

    for (int jt = 0; jt < 16; ++jt) {
        __syncthreads();
        #pragma unroll
        for (int u = 0; u < 4; u++) {
            int idx = tid + u * 256;
            int r = idx >> 4, c4 = idx & 15;
            *(uint32_t*)&sK[r][c4 * 4]     = packh2(kr[u].x, kr[u].y);
            *(uint32_t*)&sK[r][c4 * 4 + 2] = packh2(kr[u].z, kr[u].w);
            *(uint32_t*)&sV[r][c4 * 4]     = packh2(vr[u].x, vr[u].y);
            *(uint32_t*)&sV[r][c4 * 4 + 2] = packh2(vr[u].z, vr[u].w);
        }
        __syncthreads();

        if (jt < 15) {
            const float* kn = kvK + (size_t)(jt + 1) * 64 * 512;
            const float* vn = kvV + (size_t)(jt + 1) * 64 * 512;
            #pragma unroll
            for (int u = 0; u < 4; u++) {
                int idx = tid + u * 256;
                int r = idx >> 4, c4 = idx & 15;
                kr[u] = *(const float4*)(kn + (size_t)r * 512 + c4 * 4);
                vr[u] = *(const float4*)(vn + (size_t)r * 512 + c4 * 4);
            }
        }

        // S = Q @ K^T
        float s[8][4];
        #pragma unroll
        for (int nt = 0; nt < 8; nt++)
            #pragma unroll
            for (int e = 0; e < 4; e++) s[nt][e] = 0.f;
        #pragma unroll
        for (int nt = 0; nt < 8; nt++) {
            #pragma unroll
            for (int kc = 0; kc < 4; kc++) {
                uint32_t bk[2];
                bk[0] = *(const uint32_t*)&sK[nt * 8 + g][kc * 16 + 2 * c];
                bk[1] = *(const uint32_t*)&sK[nt * 8 + g][kc * 16 + 8 + 2 * c];
                mma_f16(s[nt], qa[kc], bk);
            }
        }

        // online softmax (rows g -> elems 0,1 ; rows g+8 -> elems 2,3)
        float tm0 = -1.0e30f, tm1 = -1.0e30f;
        #pragma unroll
        for (int nt = 0; nt < 8; nt++) {
            tm0 = fmaxf(tm0, fmaxf(s[nt][0], s[nt][1]));
            tm1 = fmaxf(tm1, fmaxf(s[nt][2], s[nt][3]));
        }
        tm0 = fmaxf(tm0, __shfl_xor_sync(0xffffffffu, tm0, 1));
        tm0 = fmaxf(tm0, __shfl_xor_sync(0xffffffffu, tm0, 2));
        tm1 = fmaxf(tm1, __shfl_xor_sync(0xffffffffu, tm1, 1));
        tm1 = fmaxf(tm1, __shfl_xor_sync(0xffffffffu, tm1, 2));

        float nm0 = fmaxf(m0, tm0), nm1 = fmaxf(m1, tm1);
        float al0 = __expf(m0 - nm0), al1 = __expf(m1 - nm1);
        m0 = nm0; m1 = nm1;

        // P = exp(S - m) packed to half (native A-fragment layout)
        uint32_t pk0[8], pk1[8];
        float sum0 = 0.f, sum1 = 0.f;
        #pragma unroll
        for (int nt = 0; nt < 8; nt++) {
            __half2 h0 = __floats2half2_rn(__expf(s[nt][0] - nm0), __expf(s[nt][1] - nm0));
            __half2 h1 = __floats2half2_rn(__expf(s[nt][2] - nm1), __expf(s[nt][3] - nm1));
            pk0[nt] = *(uint32_t*)&h0;
            pk1[nt] = *(uint32_t*)&h1;
            float2 r0 = __half22float2(h0), r1 = __half22float2(h1);
            sum0 += r0.x + r0.y;
            sum1 += r1.x + r1.y;
        }
        sum0 += __shfl_xor_sync(0xffffffffu, sum0, 1);
        sum0 += __shfl_xor_sync(0xffffffffu, sum0, 2);
        sum1 += __shfl_xor_sync(0xffffffffu, sum1, 1);
        sum1 += __shfl_xor_sync(0xffffffffu, sum1, 2);
        l0 = l0 * al0 + sum0;
        l1 = l1 * al1 + sum1;

        #pragma unroll
        for (int dt = 0; dt < 8; dt++) {
            o[dt][0] *= al0; o[dt][1] *= al0;
            o[dt][2] *= al1; o[dt][3] *= al1;
        }

        // O += P @ V  (A-frag straight from pk registers, zero shuffles)
        #pragma unroll
        for (int kc = 0; kc < 4; kc++) {
            uint32_t a[4] = { pk0[2 * kc], pk1[2 * kc], pk0[2 * kc + 1], pk1[2 * kc + 1] };
            #pragma unroll
            for (int dt = 0; dt < 8; dt++) {
                __half2 b0, b1;
                b0.x = sV[kc * 16 + 2 * c][dt * 8 + g];
                b0.y = sV[kc * 16 + 2 * c + 1][dt * 8 + g];
                b1.x = sV[kc * 16 + 8 + 2 * c][dt * 8 + g];
                b1.y = sV[kc * 16 + 8 + 2 * c + 1][dt * 8 + g];
                uint32_t bv[2] = { *(uint32_t*)&b0, *(uint32_t*)&b1 };
                mma_f16(o[dt], a, bv);
            }
        }
    }

    float inv0 = 1.f / l0, inv1 = 1.f / l1;
    __half* obase = g_attnh + ((size_t)(b * S_ + qb * 128 + wid * 16) * H_ + h) * 64;
    #pragma unroll
    for (int dt = 0; dt < 8; dt++) {
        *(uint32_t*)&obase[(size_t)g * 2048 + dt * 8 + 2 * c] =
            packh2(o[dt][0] * inv0, o[dt][1] * inv0);
        *(uint32_t*)&obase[(size_t)(g + 8) * 2048 + dt * 8 + 2 * c] =
            packh2(o[dt][2] * inv1, o[dt][3] * inv1);
    }
}

// ---------------------------------------------------------------------------
extern "C" void kernel_launch(void* const* d_in, const int* in_sizes, int n_in,
                              void* d_out, int out_size)
{
    (void)in_sizes; (void)n_in; (void)out_size;
    const float* x   = (const float*)d_in[0];
    const float* cb  = (const float*)d_in[1];
    const float* sb  = (const float*)d_in[2];
    const float* Wq  = (const float*)d_in[3];
    const float* Wk  = (const float*)d_in[4];
    const float* Wv  = (const float*)d_in[5];
    const float* Wo  = (const float*)d_in[6];
    float* out = (float*)d_out;

    const int GEMM_SMEM = STAGES * STG_H * 2 * 2;   // 49152 B
    cudaFuncSetAttribute(qkv_gemm_h, cudaFuncAttributeMaxDynamicSharedMemorySize, GEMM_SMEM);
    cudaFuncSetAttribute(out_gemm_h, cudaFuncAttributeMaxDynamicSharedMemorySize, GEMM_SMEM);

    __half* xh; __half* wqh; __half* wkh; __half* wvh; __half* woh;
    cudaGetSymbolAddress((void**)&xh,  g_xh);
    cudaGetSymbolAddress((void**)&wqh, g_Wqh);
    cudaGetSymbolAddress((void**)&wkh, g_Wkh);
    cudaGetSymbolAddress((void**)&wvh, g_Wvh);
    cudaGetSymbolAddress((void**)&woh, g_Woh);

    convh_kernel<<<(8388608 / 4 + 255) / 256, 256>>>(x, xh, 8388608 / 4);

    dim3 tb(32, 8);
    convT_kernel<<<dim3(2048 / 32, 2048 / 32), tb>>>(Wq, wqh, 2048, 2048);
    convT_kernel<<<dim3(512  / 32, 2048 / 32), tb>>>(Wk, wkh, 2048, 512);
    convT_kernel<<<dim3(512  / 32, 2048 / 32), tb>>>(Wv, wvh, 2048, 512);
    convT_kernel<<<dim3(2048 / 32, 2048 / 32), tb>>>(Wo, woh, 2048, 2048);

    qkv_gemm_h<<<dim3(3072 / 128, 4096 / 128), 256, GEMM_SMEM>>>();

    rope_kernel<<<(B_ * S_ * H_ * 32 + 255) / 256, 256>>>(cb, sb, 0);
    rope_kernel<<<(B_ * S_ * KVH_ * 32 + 255) / 256, 256>>>(cb, sb, 1);

    flash_h_kernel<<<dim3(S_ / 128, H_, B_), 256>>>();

    out_gemm_h<<<dim3(2048 / 128, 4096 / 128), 256, GEMM_SMEM>>>(out);
}

// round 8
// speedup vs baseline: 2.1833x; 1.1905x over previous
#include <cuda_runtime.h>
#include <cuda_fp16.h>
#include <cstdint>

#define B_   4
#define S_   1024
#define D_   2048
#define H_   32
#define KVH_ 8
#define HD_  64

#define STAGES 4
#define STG_H  3072   // halves per stage per matrix: 128 * 24

// ---------------- device scratch ----------------
__device__ __half g_qh[B_ * S_ * H_ * HD_];
__device__ __half g_kh[B_ * S_ * KVH_ * HD_];
__device__ __half g_vh[B_ * S_ * KVH_ * HD_];
__device__ __half g_attnh[B_ * S_ * H_ * HD_];
__device__ __half g_xh[B_ * S_ * D_];
__device__ __half g_Wqh[2048 * 2048];   // transposed [N][K]
__device__ __half g_Wkh[512 * 2048];
__device__ __half g_Wvh[512 * 2048];
__device__ __half g_Woh[2048 * 2048];

__device__ __forceinline__ uint32_t smem_u32(const void* p) {
    uint32_t a;
    asm("{ .reg .u64 t; cvta.to.shared.u64 t, %1; cvt.u32.u64 %0, t; }"
        : "=r"(a) : "l"(p));
    return a;
}
__device__ __forceinline__ void cpa16(uint32_t dst, const void* src) {
    asm volatile("cp.async.cg.shared.global [%0], [%1], 16;" :: "r"(dst), "l"(src));
}
#define CP_COMMIT() asm volatile("cp.async.commit_group;" ::: "memory")
#define CP_WAIT(n)  asm volatile("cp.async.wait_group %0;" :: "n"(n) : "memory")

__device__ __forceinline__ uint32_t packh2(float a, float b) {
    __half2 h = __floats2half2_rn(a, b);
    return *(uint32_t*)&h;
}
__device__ __forceinline__ void mma_f16(float* d, const uint32_t* a, const uint32_t* b) {
    asm volatile(
        "mma.sync.aligned.m16n8k16.row.col.f32.f16.f16.f32 "
        "{%0,%1,%2,%3}, {%4,%5,%6,%7}, {%8,%9}, {%0,%1,%2,%3};"
        : "+f"(d[0]), "+f"(d[1]), "+f"(d[2]), "+f"(d[3])
        : "r"(a[0]), "r"(a[1]), "r"(a[2]), "r"(a[3]), "r"(b[0]), "r"(b[1]));
}
__device__ __forceinline__ void ldsm4(uint32_t* r, uint32_t addr) {
    asm volatile("ldmatrix.sync.aligned.m8n8.x4.shared.b16 {%0,%1,%2,%3}, [%4];"
        : "=r"(r[0]), "=r"(r[1]), "=r"(r[2]), "=r"(r[3]) : "r"(addr));
}
__device__ __forceinline__ void ldsm4t(uint32_t* r, uint32_t addr) {
    asm volatile("ldmatrix.sync.aligned.m8n8.x4.trans.shared.b16 {%0,%1,%2,%3}, [%4];"
        : "=r"(r[0]), "=r"(r[1]), "=r"(r[2]), "=r"(r[3]) : "r"(addr));
}

// ---------------------------------------------------------------------------
__global__ void convh_kernel(const float* __restrict__ src,
                             __half* __restrict__ dst, int n4)
{
    int i = blockIdx.x * blockDim.x + threadIdx.x;
    if (i < n4) {
        float4 v = *(const float4*)(src + i * 4);
        uint2 u;
        u.x = packh2(v.x, v.y);
        u.y = packh2(v.z, v.w);
        *(uint2*)(dst + i * 4) = u;
    }
}

__global__ void convT_kernel(const float* __restrict__ src,
                             __half* __restrict__ dst, int rows, int cols)
{
    __shared__ float t[32][33];
    int bx = blockIdx.x * 32, by = blockIdx.y * 32;
    int tx = threadIdx.x, ty = threadIdx.y;   // 32 x 8
    #pragma unroll
    for (int j = 0; j < 32; j += 8)
        t[ty + j][tx] = src[(size_t)(by + ty + j) * cols + bx + tx];
    __syncthreads();
    #pragma unroll
    for (int j = 0; j < 32; j += 8)
        dst[(size_t)(bx + ty + j) * rows + by + tx] = __float2half(t[tx][ty + j]);
}

// ---------------------------------------------------------------------------
// fp16 mma.sync GEMM, cp.async 4-stage, ldmatrix fragments.
// CTA 128x128, 8 warps of 64x32. K=2048. Optional half output.
// ---------------------------------------------------------------------------
template<bool HALF_OUT>
__device__ __forceinline__ void gemm128_h(
    const __half* __restrict__ A, const __half* __restrict__ Wt,
    void* __restrict__ C, int ldc, int row0, int wc0)
{
    extern __shared__ __align__(16) __half smh[];
    __half* As = smh;                      // [STAGES][128][24]
    __half* Bs = smh + STAGES * STG_H;     // [STAGES][128][24] (n rows)
    const uint32_t asb = smem_u32(As), bsb = smem_u32(Bs);

    const int tid = threadIdx.x;           // 256
    const int wid = tid >> 5, lane = tid & 31;
    const int g = lane >> 2, c = lane & 3;
    const int wm = (wid & 1) * 64;
    const int wn = (wid >> 1) * 32;
    const int l7 = lane & 7, lb = (lane >> 3) & 1, lh = lane >> 4;

    const int lrow = tid >> 1, seg = tid & 1;
    const __half* asrc = A  + (size_t)(row0 + lrow) * 2048 + seg * 8;
    const __half* bsrc = Wt + (size_t)(wc0 + lrow) * 2048 + seg * 8;
    const uint32_t adst = asb + (lrow * 24 + seg * 8) * 2;
    const uint32_t bdst = bsb + (lrow * 24 + seg * 8) * 2;

    float acc[4][4][4];
    #pragma unroll
    for (int mt = 0; mt < 4; mt++)
        #pragma unroll
        for (int nt = 0; nt < 4; nt++)
            #pragma unroll
            for (int e = 0; e < 4; e++) acc[mt][nt][e] = 0.f;

    #pragma unroll
    for (int s = 0; s < STAGES - 1; s++) {
        cpa16(adst + s * STG_H * 2, asrc + s * 16);
        cpa16(bdst + s * STG_H * 2, bsrc + s * 16);
        CP_COMMIT();
    }

    int buf = 0;
    for (int i = 0; i < 128; ++i) {
        CP_WAIT(STAGES - 2);
        __syncthreads();

        const uint32_t Ab = asb + buf * STG_H * 2;
        const uint32_t Bb = bsb + buf * STG_H * 2;
        uint32_t af[4][4], bf[4][4];
        #pragma unroll
        for (int mt = 0; mt < 4; mt++)
            ldsm4(af[mt], Ab + ((wm + mt * 16 + l7 + lb * 8) * 24 + lh * 8) * 2);
        #pragma unroll
        for (int ntp = 0; ntp < 2; ntp++)
            ldsm4(bf[ntp * 2], Bb + ((wn + ntp * 16 + lh * 8 + l7) * 24 + lb * 8) * 2);
        // bf[ntp*2] = {b0(nt),b1(nt),b0(nt+1),b1(nt+1)} packed in 4 regs
        #pragma unroll
        for (int mt = 0; mt < 4; mt++) {
            #pragma unroll
            for (int ntp = 0; ntp < 2; ntp++) {
                mma_f16(acc[mt][ntp * 2],     af[mt], &bf[ntp * 2][0]);
                mma_f16(acc[mt][ntp * 2 + 1], af[mt], &bf[ntp * 2][2]);
            }
        }

        int nk = i + STAGES - 1;
        if (nk < 128) {
            int s = nk & (STAGES - 1);
            cpa16(adst + s * STG_H * 2, asrc + nk * 16);
            cpa16(bdst + s * STG_H * 2, bsrc + nk * 16);
        }
        CP_COMMIT();
        buf = (buf + 1) & (STAGES - 1);
    }

    #pragma unroll
    for (int mt = 0; mt < 4; mt++) {
        int r = row0 + wm + mt * 16 + g;
        #pragma unroll
        for (int nt = 0; nt < 4; nt++) {
            int col = wc0 + wn + nt * 8 + 2 * c;
            if (HALF_OUT) {
                __half* Ch = (__half*)C;
                *(uint32_t*)&Ch[(size_t)r * ldc + col] =
                    packh2(acc[mt][nt][0], acc[mt][nt][1]);
                *(uint32_t*)&Ch[(size_t)(r + 8) * ldc + col] =
                    packh2(acc[mt][nt][2], acc[mt][nt][3]);
            } else {
                float* Cf = (float*)C;
                *(float2*)&Cf[(size_t)r * ldc + col] =
                    make_float2(acc[mt][nt][0], acc[mt][nt][1]);
                *(float2*)&Cf[(size_t)(r + 8) * ldc + col] =
                    make_float2(acc[mt][nt][2], acc[mt][nt][3]);
            }
        }
    }
}

__global__ __launch_bounds__(256) void qkv_gemm_h()
{
    int col0 = blockIdx.x * 128, row0 = blockIdx.y * 128;
    const __half* Wt; __half* C; int ldc, wc0;
    if (col0 < 2048)      { Wt = g_Wqh; C = g_qh; ldc = 2048; wc0 = col0; }
    else if (col0 < 2560) { Wt = g_Wkh; C = g_kh; ldc = 512;  wc0 = col0 - 2048; }
    else                  { Wt = g_Wvh; C = g_vh; ldc = 512;  wc0 = col0 - 2560; }
    gemm128_h<true>(g_xh, Wt, C, ldc, row0, wc0);
}

__global__ __launch_bounds__(256) void out_gemm_h(float* __restrict__ out)
{
    int col0 = blockIdx.x * 128, row0 = blockIdx.y * 128;
    gemm128_h<false>(g_attnh, g_Woh, out, 2048, row0, col0);
}

// ---------------------------------------------------------------------------
// RoPE on half buffers, f32 math. which=0: Q (also scale 0.125), which=1: K.
// ---------------------------------------------------------------------------
__global__ void rope_h_kernel(const float* __restrict__ cosb,
                              const float* __restrict__ sinb, int which)
{
    __half* buf = which ? g_kh : g_qh;
    int nh = which ? KVH_ : H_;
    float sc = which ? 1.0f : 0.125f;
    int idx = blockIdx.x * blockDim.x + threadIdx.x;
    int total = B_ * S_ * nh * 32;
    if (idx >= total) return;
    int d = idx & 31;
    int h = (idx >> 5) % nh;
    int s = (idx / (32 * nh)) % S_;
    int b = idx / (32 * nh * S_);
    __half* row = buf + (((size_t)(b * S_ + s)) * nh + h) * 64;
    float c1 = cosb[s * 64 + d],      s1 = sinb[s * 64 + d];
    float c2 = cosb[s * 64 + d + 32], s2 = sinb[s * 64 + d + 32];
    float x1 = __half2float(row[d]), x2 = __half2float(row[d + 32]);
    row[d]      = __float2half((x1 * c1 - x2 * s1) * sc);
    row[d + 32] = __float2half((x2 * c2 + x1 * s2) * sc);
}

// ---------------------------------------------------------------------------
// Flash attention fp16: cp.async double-buffered K/V, ldmatrix fragments.
// Block = 128 q-rows x (head, batch); warp w owns rows w*16..w*16+15.
// ---------------------------------------------------------------------------
__global__ __launch_bounds__(256) void flash_h_kernel()
{
    __shared__ __align__(16) __half sK[2][64][72];
    __shared__ __align__(16) __half sV[2][64][72];

    const int tid = threadIdx.x;
    const int wid = tid >> 5, lane = tid & 31;
    const int g = lane >> 2, c = lane & 3;
    const int l7 = lane & 7, lb = (lane >> 3) & 1, lh = lane >> 4;
    const int qb = blockIdx.x, h = blockIdx.y, b = blockIdx.z;
    const int kvh = h >> 2;

    const uint32_t skb = smem_u32(&sK[0][0][0]);
    const uint32_t svb = smem_u32(&sV[0][0][0]);
    const uint32_t STG = 64 * 72 * 2;   // bytes per stage

    const __half* kvK = g_kh + ((size_t)(b * S_) * KVH_ + kvh) * 64;
    const __half* kvV = g_vh + ((size_t)(b * S_) * KVH_ + kvh) * 64;

    // per-thread cp.async slots: 2 chunks of 16B per matrix per stage
    const int r0c = tid >> 3, c8 = tid & 7;   // rows 0..31
    // chunk u: row = r0c + u*32

    // Q fragments (half, pre-scaled + roped)
    const __half* qbase = g_qh + ((size_t)(b * S_ + qb * 128 + wid * 16) * H_ + h) * 64;
    uint32_t qa[4][4];
    #pragma unroll
    for (int kc = 0; kc < 4; kc++) {
        qa[kc][0] = *(const uint32_t*)&qbase[(size_t)g * 2048       + kc * 16 + 2 * c];
        qa[kc][1] = *(const uint32_t*)&qbase[(size_t)(g + 8) * 2048 + kc * 16 + 2 * c];
        qa[kc][2] = *(const uint32_t*)&qbase[(size_t)g * 2048       + kc * 16 + 8 + 2 * c];
        qa[kc][3] = *(const uint32_t*)&qbase[(size_t)(g + 8) * 2048 + kc * 16 + 8 + 2 * c];
    }

    float o[8][4];
    #pragma unroll
    for (int dt = 0; dt < 8; dt++)
        #pragma unroll
        for (int e = 0; e < 4; e++) o[dt][e] = 0.f;
    float m0 = -1.0e30f, m1 = -1.0e30f, l0 = 0.f, l1 = 0.f;

    // prologue: stages for tiles 0 and 1
    #pragma unroll
    for (int s = 0; s < 2; s++) {
        const __half* kb = kvK + (size_t)s * 64 * 512;
        const __half* vb = kvV + (size_t)s * 64 * 512;
        #pragma unroll
        for (int u = 0; u < 2; u++) {
            int r = r0c + u * 32;
            cpa16(skb + s * STG + (r * 72 + c8 * 8) * 2, kb + (size_t)r * 512 + c8 * 8);
            cpa16(svb + s * STG + (r * 72 + c8 * 8) * 2, vb + (size_t)r * 512 + c8 * 8);
        }
        CP_COMMIT();
    }

    for (int jt = 0; jt < 16; ++jt) {
        const int buf = jt & 1;
        if (jt < 15) { CP_WAIT(1); } else { CP_WAIT(0); }
        __syncthreads();

        const uint32_t Kb = skb + buf * STG;
        const uint32_t Vb = svb + buf * STG;

        // S = Q @ K^T  (K b-frags via ldmatrix non-trans)
        float s[8][4];
        #pragma unroll
        for (int nt = 0; nt < 8; nt++)
            #pragma unroll
            for (int e = 0; e < 4; e++) s[nt][e] = 0.f;
        #pragma unroll
        for (int nt = 0; nt < 8; nt++) {
            #pragma unroll
            for (int kc2 = 0; kc2 < 2; kc2++) {
                uint32_t bk[4];
                ldsm4(bk, Kb + ((nt * 8 + l7) * 72 + kc2 * 32 + (lane >> 3) * 8) * 2);
                mma_f16(s[nt], qa[kc2 * 2],     &bk[0]);
                mma_f16(s[nt], qa[kc2 * 2 + 1], &bk[2]);
            }
        }

        // online softmax
        float tm0 = -1.0e30f, tm1 = -1.0e30f;
        #pragma unroll
        for (int nt = 0; nt < 8; nt++) {
            tm0 = fmaxf(tm0, fmaxf(s[nt][0], s[nt][1]));
            tm1 = fmaxf(tm1, fmaxf(s[nt][2], s[nt][3]));
        }
        tm0 = fmaxf(tm0, __shfl_xor_sync(0xffffffffu, tm0, 1));
        tm0 = fmaxf(tm0, __shfl_xor_sync(0xffffffffu, tm0, 2));
        tm1 = fmaxf(tm1, __shfl_xor_sync(0xffffffffu, tm1, 1));
        tm1 = fmaxf(tm1, __shfl_xor_sync(0xffffffffu, tm1, 2));

        float nm0 = fmaxf(m0, tm0), nm1 = fmaxf(m1, tm1);
        float al0 = __expf(m0 - nm0), al1 = __expf(m1 - nm1);
        m0 = nm0; m1 = nm1;

        uint32_t pk0[8], pk1[8];
        float sum0 = 0.f, sum1 = 0.f;
        #pragma unroll
        for (int nt = 0; nt < 8; nt++) {
            __half2 h0 = __floats2half2_rn(__expf(s[nt][0] - nm0), __expf(s[nt][1] - nm0));
            __half2 h1 = __floats2half2_rn(__expf(s[nt][2] - nm1), __expf(s[nt][3] - nm1));
            pk0[nt] = *(uint32_t*)&h0;
            pk1[nt] = *(uint32_t*)&h1;
            float2 r0 = __half22float2(h0), r1 = __half22float2(h1);
            sum0 += r0.x + r0.y;
            sum1 += r1.x + r1.y;
        }
        sum0 += __shfl_xor_sync(0xffffffffu, sum0, 1);
        sum0 += __shfl_xor_sync(0xffffffffu, sum0, 2);
        sum1 += __shfl_xor_sync(0xffffffffu, sum1, 1);
        sum1 += __shfl_xor_sync(0xffffffffu, sum1, 2);
        l0 = l0 * al0 + sum0;
        l1 = l1 * al1 + sum1;

        #pragma unroll
        for (int dt = 0; dt < 8; dt++) {
            o[dt][0] *= al0; o[dt][1] *= al0;
            o[dt][2] *= al1; o[dt][3] *= al1;
        }

        // O += P @ V  (V b-frags via ldmatrix.trans)
        #pragma unroll
        for (int kc = 0; kc < 4; kc++) {
            uint32_t a[4] = { pk0[2 * kc], pk1[2 * kc], pk0[2 * kc + 1], pk1[2 * kc + 1] };
            #pragma unroll
            for (int dtp = 0; dtp < 4; dtp++) {
                uint32_t bv[4];
                ldsm4t(bv, Vb + ((kc * 16 + lb * 8 + l7) * 72 + dtp * 16 + lh * 8) * 2);
                mma_f16(o[dtp * 2],     a, &bv[0]);
                mma_f16(o[dtp * 2 + 1], a, &bv[2]);
            }
        }

        __syncthreads();
        if (jt + 2 < 16) {
            const __half* kb = kvK + (size_t)(jt + 2) * 64 * 512;
            const __half* vb = kvV + (size_t)(jt + 2) * 64 * 512;
            #pragma unroll
            for (int u = 0; u < 2; u++) {
                int r = r0c + u * 32;
                cpa16(skb + buf * STG + (r * 72 + c8 * 8) * 2, kb + (size_t)r * 512 + c8 * 8);
                cpa16(svb + buf * STG + (r * 72 + c8 * 8) * 2, vb + (size_t)r * 512 + c8 * 8);
            }
            CP_COMMIT();
        }
    }

    float inv0 = 1.f / l0, inv1 = 1.f / l1;
    __half* obase = g_attnh + ((size_t)(b * S_ + qb * 128 + wid * 16) * H_ + h) * 64;
    #pragma unroll
    for (int dt = 0; dt < 8; dt++) {
        *(uint32_t*)&obase[(size_t)g * 2048 + dt * 8 + 2 * c] =
            packh2(o[dt][0] * inv0, o[dt][1] * inv0);
        *(uint32_t*)&obase[(size_t)(g + 8) * 2048 + dt * 8 + 2 * c] =
            packh2(o[dt][2] * inv1, o[dt][3] * inv1);
    }
}

// ---------------------------------------------------------------------------
extern "C" void kernel_launch(void* const* d_in, const int* in_sizes, int n_in,
                              void* d_out, int out_size)
{
    (void)in_sizes; (void)n_in; (void)out_size;
    const float* x   = (const float*)d_in[0];
    const float* cb  = (const float*)d_in[1];
    const float* sb  = (const float*)d_in[2];
    const float* Wq  = (const float*)d_in[3];
    const float* Wk  = (const float*)d_in[4];
    const float* Wv  = (const float*)d_in[5];
    const float* Wo  = (const float*)d_in[6];
    float* out = (float*)d_out;

    const int GEMM_SMEM = STAGES * STG_H * 2 * 2;   // 49152 B
    cudaFuncSetAttribute(qkv_gemm_h, cudaFuncAttributeMaxDynamicSharedMemorySize, GEMM_SMEM);
    cudaFuncSetAttribute(out_gemm_h, cudaFuncAttributeMaxDynamicSharedMemorySize, GEMM_SMEM);

    __half* xh; __half* wqh; __half* wkh; __half* wvh; __half* woh;
    cudaGetSymbolAddress((void**)&xh,  g_xh);
    cudaGetSymbolAddress((void**)&wqh, g_Wqh);
    cudaGetSymbolAddress((void**)&wkh, g_Wkh);
    cudaGetSymbolAddress((void**)&wvh, g_Wvh);
    cudaGetSymbolAddress((void**)&woh, g_Woh);

    convh_kernel<<<(8388608 / 4 + 255) / 256, 256>>>(x, xh, 8388608 / 4);

    dim3 tb(32, 8);
    convT_kernel<<<dim3(2048 / 32, 2048 / 32), tb>>>(Wq, wqh, 2048, 2048);
    convT_kernel<<<dim3(512  / 32, 2048 / 32), tb>>>(Wk, wkh, 2048, 512);
    convT_kernel<<<dim3(512  / 32, 2048 / 32), tb>>>(Wv, wvh, 2048, 512);
    convT_kernel<<<dim3(2048 / 32, 2048 / 32), tb>>>(Wo, woh, 2048, 2048);

    qkv_gemm_h<<<dim3(3072 / 128, 4096 / 128), 256, GEMM_SMEM>>>();

    rope_h_kernel<<<(B_ * S_ * H_ * 32 + 255) / 256, 256>>>(cb, sb, 0);
    rope_h_kernel<<<(B_ * S_ * KVH_ * 32 + 255) / 256, 256>>>(cb, sb, 1);

    flash_h_kernel<<<dim3(S_ / 128, H_, B_), 256>>>();

    out_gemm_h<<<dim3(2048 / 128, 4096 / 128), 256, GEMM_SMEM>>>(out);
}

// round 10
// speedup vs baseline: 2.2687x; 1.0391x over previous
#include <cuda_runtime.h>
#include <cuda_fp16.h>
#include <cstdint>

#define B_   4
#define S_   1024
#define D_   2048
#define H_   32
#define KVH_ 8
#define HD_  64

#define STAGES 4
#define STG_H  3072   // halves per stage per matrix: 128 * 24

// ---------------- device scratch ----------------
__device__ __half g_qh[B_ * S_ * H_ * HD_];   // raw Q (rope applied in flash)
__device__ __half g_kh[B_ * S_ * KVH_ * HD_]; // roped K
__device__ __half g_vh[B_ * S_ * KVH_ * HD_];
__device__ __half g_attnh[B_ * S_ * H_ * HD_];
__device__ __half g_xh[B_ * S_ * D_];
__device__ __half g_Wqh[2048 * 2048];   // transposed [N][K]
__device__ __half g_Wkh[512 * 2048];
__device__ __half g_Wvh[512 * 2048];
__device__ __half g_Woh[2048 * 2048];

__device__ __forceinline__ uint32_t smem_u32(const void* p) {
    uint32_t a;
    asm("{ .reg .u64 t; cvta.to.shared.u64 t, %1; cvt.u32.u64 %0, t; }"
        : "=r"(a) : "l"(p));
    return a;
}
__device__ __forceinline__ void cpa16(uint32_t dst, const void* src) {
    asm volatile("cp.async.cg.shared.global [%0], [%1], 16;" :: "r"(dst), "l"(src));
}
#define CP_COMMIT() asm volatile("cp.async.commit_group;" ::: "memory")
#define CP_WAIT(n)  asm volatile("cp.async.wait_group %0;" :: "n"(n) : "memory")

__device__ __forceinline__ uint32_t packh2(float a, float b) {
    __half2 h = __floats2half2_rn(a, b);
    return *(uint32_t*)&h;
}
__device__ __forceinline__ void mma_f16(float* d, const uint32_t* a, const uint32_t* b) {
    asm volatile(
        "mma.sync.aligned.m16n8k16.row.col.f32.f16.f16.f32 "
        "{%0,%1,%2,%3}, {%4,%5,%6,%7}, {%8,%9}, {%0,%1,%2,%3};"
        : "+f"(d[0]), "+f"(d[1]), "+f"(d[2]), "+f"(d[3])
        : "r"(a[0]), "r"(a[1]), "r"(a[2]), "r"(a[3]), "r"(b[0]), "r"(b[1]));
}
__device__ __forceinline__ void ldsm4(uint32_t* r, uint32_t addr) {
    asm volatile("ldmatrix.sync.aligned.m8n8.x4.shared.b16 {%0,%1,%2,%3}, [%4];"
        : "=r"(r[0]), "=r"(r[1]), "=r"(r[2]), "=r"(r[3]) : "r"(addr));
}
__device__ __forceinline__ void ldsm4t(uint32_t* r, uint32_t addr) {
    asm volatile("ldmatrix.sync.aligned.m8n8.x4.trans.shared.b16 {%0,%1,%2,%3}, [%4];"
        : "=r"(r[0]), "=r"(r[1]), "=r"(r[2]), "=r"(r[3]) : "r"(addr));
}

// ---------------------------------------------------------------------------
__global__ void convh_kernel(const float* __restrict__ src,
                             __half* __restrict__ dst, int n4)
{
    int i = blockIdx.x * blockDim.x + threadIdx.x;
    if (i < n4) {
        float4 v = *(const float4*)(src + i * 4);
        uint2 u;
        u.x = packh2(v.x, v.y);
        u.y = packh2(v.z, v.w);
        *(uint2*)(dst + i * 4) = u;
    }
}

__global__ void convT_kernel(const float* __restrict__ src,
                             __half* __restrict__ dst, int rows, int cols)
{
    __shared__ float t[32][33];
    int bx = blockIdx.x * 32, by = blockIdx.y * 32;
    int tx = threadIdx.x, ty = threadIdx.y;   // 32 x 8
    #pragma unroll
    for (int j = 0; j < 32; j += 8)
        t[ty + j][tx] = src[(size_t)(by + ty + j) * cols + bx + tx];
    __syncthreads();
    #pragma unroll
    for (int j = 0; j < 32; j += 8)
        dst[(size_t)(bx + ty + j) * rows + by + tx] = __float2half(t[tx][ty + j]);
}

// ---------------------------------------------------------------------------
// fp16 mma.sync GEMM, cp.async 4-stage, ldmatrix fragments. (unchanged R8)
// ---------------------------------------------------------------------------
template<bool HALF_OUT>
__device__ __forceinline__ void gemm128_h(
    const __half* __restrict__ A, const __half* __restrict__ Wt,
    void* __restrict__ C, int ldc, int row0, int wc0)
{
    extern __shared__ __align__(16) __half smh[];
    __half* As = smh;
    __half* Bs = smh + STAGES * STG_H;
    const uint32_t asb = smem_u32(As), bsb = smem_u32(Bs);

    const int tid = threadIdx.x;
    const int wid = tid >> 5, lane = tid & 31;
    const int g = lane >> 2, c = lane & 3;
    const int wm = (wid & 1) * 64;
    const int wn = (wid >> 1) * 32;
    const int l7 = lane & 7, lb = (lane >> 3) & 1, lh = lane >> 4;

    const int lrow = tid >> 1, seg = tid & 1;
    const __half* asrc = A  + (size_t)(row0 + lrow) * 2048 + seg * 8;
    const __half* bsrc = Wt + (size_t)(wc0 + lrow) * 2048 + seg * 8;
    const uint32_t adst = asb + (lrow * 24 + seg * 8) * 2;
    const uint32_t bdst = bsb + (lrow * 24 + seg * 8) * 2;

    float acc[4][4][4];
    #pragma unroll
    for (int mt = 0; mt < 4; mt++)
        #pragma unroll
        for (int nt = 0; nt < 4; nt++)
            #pragma unroll
            for (int e = 0; e < 4; e++) acc[mt][nt][e] = 0.f;

    #pragma unroll
    for (int s = 0; s < STAGES - 1; s++) {
        cpa16(adst + s * STG_H * 2, asrc + s * 16);
        cpa16(bdst + s * STG_H * 2, bsrc + s * 16);
        CP_COMMIT();
    }

    int buf = 0;
    for (int i = 0; i < 128; ++i) {
        CP_WAIT(STAGES - 2);
        __syncthreads();

        const uint32_t Ab = asb + buf * STG_H * 2;
        const uint32_t Bb = bsb + buf * STG_H * 2;
        uint32_t af[4][4], bf[4][4];
        #pragma unroll
        for (int mt = 0; mt < 4; mt++)
            ldsm4(af[mt], Ab + ((wm + mt * 16 + l7 + lb * 8) * 24 + lh * 8) * 2);
        #pragma unroll
        for (int ntp = 0; ntp < 2; ntp++)
            ldsm4(bf[ntp * 2], Bb + ((wn + ntp * 16 + lh * 8 + l7) * 24 + lb * 8) * 2);
        #pragma unroll
        for (int mt = 0; mt < 4; mt++) {
            #pragma unroll
            for (int ntp = 0; ntp < 2; ntp++) {
                mma_f16(acc[mt][ntp * 2],     af[mt], &bf[ntp * 2][0]);
                mma_f16(acc[mt][ntp * 2 + 1], af[mt], &bf[ntp * 2][2]);
            }
        }

        int nk = i + STAGES - 1;
        if (nk < 128) {
            int s = nk & (STAGES - 1);
            cpa16(adst + s * STG_H * 2, asrc + nk * 16);
            cpa16(bdst + s * STG_H * 2, bsrc + nk * 16);
        }
        CP_COMMIT();
        buf = (buf + 1) & (STAGES - 1);
    }

    #pragma unroll
    for (int mt = 0; mt < 4; mt++) {
        int r = row0 + wm + mt * 16 + g;
        #pragma unroll
        for (int nt = 0; nt < 4; nt++) {
            int col = wc0 + wn + nt * 8 + 2 * c;
            if (HALF_OUT) {
                __half* Ch = (__half*)C;
                *(uint32_t*)&Ch[(size_t)r * ldc + col] =
                    packh2(acc[mt][nt][0], acc[mt][nt][1]);
                *(uint32_t*)&Ch[(size_t)(r + 8) * ldc + col] =
                    packh2(acc[mt][nt][2], acc[mt][nt][3]);
            } else {
                float* Cf = (float*)C;
                *(float2*)&Cf[(size_t)r * ldc + col] =
                    make_float2(acc[mt][nt][0], acc[mt][nt][1]);
                *(float2*)&Cf[(size_t)(r + 8) * ldc + col] =
                    make_float2(acc[mt][nt][2], acc[mt][nt][3]);
            }
        }
    }
}

__global__ __launch_bounds__(256) void qkv_gemm_h()
{
    int col0 = blockIdx.x * 128, row0 = blockIdx.y * 128;
    const __half* Wt; __half* C; int ldc, wc0;
    if (col0 < 2048)      { Wt = g_Wqh; C = g_qh; ldc = 2048; wc0 = col0; }
    else if (col0 < 2560) { Wt = g_Wkh; C = g_kh; ldc = 512;  wc0 = col0 - 2048; }
    else                  { Wt = g_Wvh; C = g_vh; ldc = 512;  wc0 = col0 - 2560; }
    gemm128_h<true>(g_xh, Wt, C, ldc, row0, wc0);
}

__global__ __launch_bounds__(256) void out_gemm_h(float* __restrict__ out)
{
    int col0 = blockIdx.x * 128, row0 = blockIdx.y * 128;
    gemm128_h<false>(g_attnh, g_Woh, out, 2048, row0, col0);
}

// ---------------------------------------------------------------------------
// RoPE on half K buffer (Q rope fused into flash)
// ---------------------------------------------------------------------------
__global__ void rope_k_kernel(const float* __restrict__ cosb,
                              const float* __restrict__ sinb)
{
    int idx = blockIdx.x * blockDim.x + threadIdx.x;
    int total = B_ * S_ * KVH_ * 32;
    if (idx >= total) return;
    int d = idx & 31;
    int h = (idx >> 5) % KVH_;
    int s = (idx / (32 * KVH_)) % S_;
    int b = idx / (32 * KVH_ * S_);
    __half* row = g_kh + (((size_t)(b * S_ + s)) * KVH_ + h) * 64;
    float c1 = cosb[s * 64 + d],      s1 = sinb[s * 64 + d];
    float c2 = cosb[s * 64 + d + 32], s2 = sinb[s * 64 + d + 32];
    float x1 = __half2float(row[d]), x2 = __half2float(row[d + 32]);
    row[d]      = __float2half(x1 * c1 - x2 * s1);
    row[d + 32] = __float2half(x2 * c2 + x1 * s2);
}

// ---------------------------------------------------------------------------
// Flash attention fp16: 3-stage cp.async (ONE barrier per tile), ldmatrix,
// RoPE-Q + scale fused into the Q fragment load.
// ---------------------------------------------------------------------------
#define FSTG 9216   // bytes per stage per matrix: 64*72*2

__global__ __launch_bounds__(256) void flash_h_kernel(
    const float* __restrict__ cosb, const float* __restrict__ sinb)
{
    extern __shared__ __align__(16) __half fsm[];
    const uint32_t skb = smem_u32(fsm);           // 3 K stages
    const uint32_t svb = skb + 3 * FSTG;          // 3 V stages

    const int tid = threadIdx.x;
    const int wid = tid >> 5, lane = tid & 31;
    const int g = lane >> 2, c = lane & 3;
    const int l7 = lane & 7, lb = (lane >> 3) & 1, lh = lane >> 4;
    const int qb = blockIdx.x, h = blockIdx.y, b = blockIdx.z;
    const int kvh = h >> 2;

    const __half* kvK = g_kh + ((size_t)(b * S_) * KVH_ + kvh) * 64;
    const __half* kvV = g_vh + ((size_t)(b * S_) * KVH_ + kvh) * 64;
    const int r0c = tid >> 3, c8 = tid & 7;

    // ---- Q fragments with fused RoPE + 0.125 scale ----
    const __half* qr = g_qh + ((size_t)(b * S_ + qb * 128 + wid * 16) * H_ + h) * 64;
    const int s0 = qb * 128 + wid * 16 + g;
    uint32_t qa[4][4];
    #pragma unroll
    for (int kc = 0; kc < 4; kc++) {
        #pragma unroll
        for (int e = 0; e < 4; e++) {
            const int rr = (e & 1) ? (g + 8) : g;          // local row
            const int sidx = (e & 1) ? (s0 + 8) : s0;      // seq position
            const int d = kc * 16 + 2 * c + ((e >> 1) ? 8 : 0);
            __half2 qv = *(const __half2*)&qr[(size_t)rr * 2048 + d];
            __half2 pv = *(const __half2*)&qr[(size_t)rr * 2048 + (d ^ 32)];
            float2 cs = *(const float2*)&cosb[sidx * 64 + d];
            float2 sn = *(const float2*)&sinb[sidx * 64 + d];
            float sgn = (d < 32) ? -1.f : 1.f;
            float r0v = (__half2float(qv.x) * cs.x + sgn * __half2float(pv.x) * sn.x) * 0.125f;
            float r1v = (__half2float(qv.y) * cs.y + sgn * __half2float(pv.y) * sn.y) * 0.125f;
            qa[kc][e] = packh2(r0v, r1v);
        }
    }

    float o[8][4];
    #pragma unroll
    for (int dt = 0; dt < 8; dt++)
        #pragma unroll
        for (int e = 0; e < 4; e++) o[dt][e] = 0.f;
    float m0 = -1.0e30f, m1 = -1.0e30f, l0 = 0.f, l1 = 0.f;

    // prologue: stages 0, 1
    #pragma unroll
    for (int s = 0; s < 2; s++) {
        const __half* kb = kvK + (size_t)s * 64 * 512;
        const __half* vb = kvV + (size_t)s * 64 * 512;
        #pragma unroll
        for (int u = 0; u < 2; u++) {
            int r = r0c + u * 32;
            cpa16(skb + s * FSTG + (r * 72 + c8 * 8) * 2, kb + (size_t)r * 512 + c8 * 8);
            cpa16(svb + s * FSTG + (r * 72 + c8 * 8) * 2, vb + (size_t)r * 512 + c8 * 8);
        }
        CP_COMMIT();
    }

    int stage = 0;
    for (int jt = 0; jt < 16; ++jt) {
        CP_WAIT(1);
        __syncthreads();   // single barrier per tile (3-stage safety)

        const uint32_t Kb = skb + stage * FSTG;
        const uint32_t Vb = svb + stage * FSTG;

        // S = Q @ K^T
        float s[8][4];
        #pragma unroll
        for (int nt = 0; nt < 8; nt++)
            #pragma unroll
            for (int e = 0; e < 4; e++) s[nt][e] = 0.f;
        #pragma unroll
        for (int nt = 0; nt < 8; nt++) {
            #pragma unroll
            for (int kc2 = 0; kc2 < 2; kc2++) {
                uint32_t bk[4];
                ldsm4(bk, Kb + ((nt * 8 + l7) * 72 + kc2 * 32 + (lane >> 3) * 8) * 2);
                mma_f16(s[nt], qa[kc2 * 2],     &bk[0]);
                mma_f16(s[nt], qa[kc2 * 2 + 1], &bk[2]);
            }
        }

        // online softmax
        float tm0 = -1.0e30f, tm1 = -1.0e30f;
        #pragma unroll
        for (int nt = 0; nt < 8; nt++) {
            tm0 = fmaxf(tm0, fmaxf(s[nt][0], s[nt][1]));
            tm1 = fmaxf(tm1, fmaxf(s[nt][2], s[nt][3]));
        }
        tm0 = fmaxf(tm0, __shfl_xor_sync(0xffffffffu, tm0, 1));
        tm0 = fmaxf(tm0, __shfl_xor_sync(0xffffffffu, tm0, 2));
        tm1 = fmaxf(tm1, __shfl_xor_sync(0xffffffffu, tm1, 1));
        tm1 = fmaxf(tm1, __shfl_xor_sync(0xffffffffu, tm1, 2));

        float nm0 = fmaxf(m0, tm0), nm1 = fmaxf(m1, tm1);
        float al0 = __expf(m0 - nm0), al1 = __expf(m1 - nm1);
        m0 = nm0; m1 = nm1;

        uint32_t pk0[8], pk1[8];
        float sum0 = 0.f, sum1 = 0.f;
        #pragma unroll
        for (int nt = 0; nt < 8; nt++) {
            __half2 h0 = __floats2half2_rn(__expf(s[nt][0] - nm0), __expf(s[nt][1] - nm0));
            __half2 h1 = __floats2half2_rn(__expf(s[nt][2] - nm1), __expf(s[nt][3] - nm1));
            pk0[nt] = *(uint32_t*)&h0;
            pk1[nt] = *(uint32_t*)&h1;
            float2 r0 = __half22float2(h0), r1 = __half22float2(h1);
            sum0 += r0.x + r0.y;
            sum1 += r1.x + r1.y;
        }
        sum0 += __shfl_xor_sync(0xffffffffu, sum0, 1);
        sum0 += __shfl_xor_sync(0xffffffffu, sum0, 2);
        sum1 += __shfl_xor_sync(0xffffffffu, sum1, 1);
        sum1 += __shfl_xor_sync(0xffffffffu, sum1, 2);
        l0 = l0 * al0 + sum0;
        l1 = l1 * al1 + sum1;

        #pragma unroll
        for (int dt = 0; dt < 8; dt++) {
            o[dt][0] *= al0; o[dt][1] *= al0;
            o[dt][2] *= al1; o[dt][3] *= al1;
        }

        // O += P @ V
        #pragma unroll
        for (int kc = 0; kc < 4; kc++) {
            uint32_t a[4] = { pk0[2 * kc], pk1[2 * kc], pk0[2 * kc + 1], pk1[2 * kc + 1] };
            #pragma unroll
            for (int dtp = 0; dtp < 4; dtp++) {
                uint32_t bv[4];
                ldsm4t(bv, Vb + ((kc * 16 + lb * 8 + l7) * 72 + dtp * 16 + lh * 8) * 2);
                mma_f16(o[dtp * 2],     a, &bv[0]);
                mma_f16(o[dtp * 2 + 1], a, &bv[2]);
            }
        }

        // prefetch tile jt+2 into stage (jt+2)%3 — FIXED ring index
        if (jt + 2 < 16) {
            const int ws = stage;   // (stage + 2) % 3 == (stage - 1 + 3) % 3? NO:
            // stage = jt % 3; target = (jt+2) % 3. Compute branch-free:
            const int wsf = (stage + 2 >= 3) ? (stage + 2 - 3) : (stage + 2);
            (void)ws;
            const __half* kb = kvK + (size_t)(jt + 2) * 64 * 512;
            const __half* vb = kvV + (size_t)(jt + 2) * 64 * 512;
            #pragma unroll
            for (int u = 0; u < 2; u++) {
                int r = r0c + u * 32;
                cpa16(skb + wsf * FSTG + (r * 72 + c8 * 8) * 2, kb + (size_t)r * 512 + c8 * 8);
                cpa16(svb + wsf * FSTG + (r * 72 + c8 * 8) * 2, vb + (size_t)r * 512 + c8 * 8);
            }
        }
        CP_COMMIT();
        stage = (stage + 1 >= 3) ? 0 : stage + 1;
    }

    float inv0 = 1.f / l0, inv1 = 1.f / l1;
    __half* obase = g_attnh + ((size_t)(b * S_ + qb * 128 + wid * 16) * H_ + h) * 64;
    #pragma unroll
    for (int dt = 0; dt < 8; dt++) {
        *(uint32_t*)&obase[(size_t)g * 2048 + dt * 8 + 2 * c] =
            packh2(o[dt][0] * inv0, o[dt][1] * inv0);
        *(uint32_t*)&obase[(size_t)(g + 8) * 2048 + dt * 8 + 2 * c] =
            packh2(o[dt][2] * inv1, o[dt][3] * inv1);
    }
}

// ---------------------------------------------------------------------------
extern "C" void kernel_launch(void* const* d_in, const int* in_sizes, int n_in,
                              void* d_out, int out_size)
{
    (void)in_sizes; (void)n_in; (void)out_size;
    const float* x   = (const float*)d_in[0];
    const float* cb  = (const float*)d_in[1];
    const float* sb  = (const float*)d_in[2];
    const float* Wq  = (const float*)d_in[3];
    const float* Wk  = (const float*)d_in[4];
    const float* Wv  = (const float*)d_in[5];
    const float* Wo  = (const float*)d_in[6];
    float* out = (float*)d_out;

    const int GEMM_SMEM  = STAGES * STG_H * 2 * 2;   // 49152 B
    const int FLASH_SMEM = 6 * FSTG;                  // 55296 B
    cudaFuncSetAttribute(qkv_gemm_h, cudaFuncAttributeMaxDynamicSharedMemorySize, GEMM_SMEM);
    cudaFuncSetAttribute(out_gemm_h, cudaFuncAttributeMaxDynamicSharedMemorySize, GEMM_SMEM);
    cudaFuncSetAttribute(flash_h_kernel, cudaFuncAttributeMaxDynamicSharedMemorySize, FLASH_SMEM);

    __half* xh; __half* wqh; __half* wkh; __half* wvh; __half* woh;
    cudaGetSymbolAddress((void**)&xh,  g_xh);
    cudaGetSymbolAddress((void**)&wqh, g_Wqh);
    cudaGetSymbolAddress((void**)&wkh, g_Wkh);
    cudaGetSymbolAddress((void**)&wvh, g_Wvh);
    cudaGetSymbolAddress((void**)&woh, g_Woh);

    convh_kernel<<<(8388608 / 4 + 255) / 256, 256>>>(x, xh, 8388608 / 4);

    dim3 tb(32, 8);
    convT_kernel<<<dim3(2048 / 32, 2048 / 32), tb>>>(Wq, wqh, 2048, 2048);
    convT_kernel<<<dim3(512  / 32, 2048 / 32), tb>>>(Wk, wkh, 2048, 512);
    convT_kernel<<<dim3(512  / 32, 2048 / 32), tb>>>(Wv, wvh, 2048, 512);
    convT_kernel<<<dim3(2048 / 32, 2048 / 32), tb>>>(Wo, woh, 2048, 2048);

    qkv_gemm_h<<<dim3(3072 / 128, 4096 / 128), 256, GEMM_SMEM>>>();

    rope_k_kernel<<<(B_ * S_ * KVH_ * 32 + 255) / 256, 256>>>(cb, sb);

    flash_h_kernel<<<dim3(S_ / 128, H_, B_), 256, FLASH_SMEM>>>(cb, sb);

    out_gemm_h<<<dim3(2048 / 128, 4096 / 128), 256, GEMM_SMEM>>>(out);
}

// round 11
// speedup vs baseline: 2.4269x; 1.0697x over previous
#include <cuda_runtime.h>
#include <cuda_fp16.h>
#include <cstdint>

#define B_   4
#define S_   1024
#define D_   2048
#define H_   32
#define KVH_ 8
#define HD_  64

// GEMM: K-step 32, 3 smem stages
#define NSTG   3
#define ASTG32 5120   // halves per stage per matrix: 128 * 40

// ---------------- device scratch ----------------
__device__ __half g_qh[B_ * S_ * H_ * HD_];   // raw Q (rope applied in flash)
__device__ __half g_kh[B_ * S_ * KVH_ * HD_]; // roped K
__device__ __half g_vh[B_ * S_ * KVH_ * HD_];
__device__ __half g_attnh[B_ * S_ * H_ * HD_];
__device__ __half g_xh[B_ * S_ * D_];
__device__ __half g_Wqh[2048 * 2048];   // transposed [N][K]
__device__ __half g_Wkh[512 * 2048];
__device__ __half g_Wvh[512 * 2048];
__device__ __half g_Woh[2048 * 2048];

__device__ __forceinline__ uint32_t smem_u32(const void* p) {
    uint32_t a;
    asm("{ .reg .u64 t; cvta.to.shared.u64 t, %1; cvt.u32.u64 %0, t; }"
        : "=r"(a) : "l"(p));
    return a;
}
__device__ __forceinline__ void cpa16(uint32_t dst, const void* src) {
    asm volatile("cp.async.cg.shared.global [%0], [%1], 16;" :: "r"(dst), "l"(src));
}
#define CP_COMMIT() asm volatile("cp.async.commit_group;" ::: "memory")
#define CP_WAIT(n)  asm volatile("cp.async.wait_group %0;" :: "n"(n) : "memory")

__device__ __forceinline__ uint32_t packh2(float a, float b) {
    __half2 h = __floats2half2_rn(a, b);
    return *(uint32_t*)&h;
}
__device__ __forceinline__ void mma_f16(float* d, const uint32_t* a, const uint32_t* b) {
    asm volatile(
        "mma.sync.aligned.m16n8k16.row.col.f32.f16.f16.f32 "
        "{%0,%1,%2,%3}, {%4,%5,%6,%7}, {%8,%9}, {%0,%1,%2,%3};"
        : "+f"(d[0]), "+f"(d[1]), "+f"(d[2]), "+f"(d[3])
        : "r"(a[0]), "r"(a[1]), "r"(a[2]), "r"(a[3]), "r"(b[0]), "r"(b[1]));
}
__device__ __forceinline__ void ldsm4(uint32_t* r, uint32_t addr) {
    asm volatile("ldmatrix.sync.aligned.m8n8.x4.shared.b16 {%0,%1,%2,%3}, [%4];"
        : "=r"(r[0]), "=r"(r[1]), "=r"(r[2]), "=r"(r[3]) : "r"(addr));
}
__device__ __forceinline__ void ldsm4t(uint32_t* r, uint32_t addr) {
    asm volatile("ldmatrix.sync.aligned.m8n8.x4.trans.shared.b16 {%0,%1,%2,%3}, [%4];"
        : "=r"(r[0]), "=r"(r[1]), "=r"(r[2]), "=r"(r[3]) : "r"(addr));
}

// ---------------------------------------------------------------------------
__global__ void convh_kernel(const float* __restrict__ src,
                             __half* __restrict__ dst, int n4)
{
    int i = blockIdx.x * blockDim.x + threadIdx.x;
    if (i < n4) {
        float4 v = *(const float4*)(src + i * 4);
        uint2 u;
        u.x = packh2(v.x, v.y);
        u.y = packh2(v.z, v.w);
        *(uint2*)(dst + i * 4) = u;
    }
}

// All four weight transposes in one launch. rows=2048 always; z selects matrix.
__global__ void convT_all_kernel(const float* __restrict__ Wq, const float* __restrict__ Wk,
                                 const float* __restrict__ Wv, const float* __restrict__ Wo,
                                 __half* __restrict__ dq, __half* __restrict__ dk,
                                 __half* __restrict__ dv, __half* __restrict__ dob)
{
    const int z = blockIdx.z;
    const float* src; __half* dst; int cols;
    if (z == 0)      { src = Wq; dst = dq;  cols = 2048; }
    else if (z == 1) { src = Wk; dst = dk;  cols = 512;  }
    else if (z == 2) { src = Wv; dst = dv;  cols = 512;  }
    else             { src = Wo; dst = dob; cols = 2048; }
    int bx = blockIdx.x * 32, by = blockIdx.y * 32;
    if (bx >= cols) return;

    __shared__ float t[32][33];
    int tx = threadIdx.x, ty = threadIdx.y;   // 32 x 8
    #pragma unroll
    for (int j = 0; j < 32; j += 8)
        t[ty + j][tx] = src[(size_t)(by + ty + j) * cols + bx + tx];
    __syncthreads();
    #pragma unroll
    for (int j = 0; j < 32; j += 8)
        dst[(size_t)(bx + ty + j) * 2048 + by + tx] = __float2half(t[tx][ty + j]);
}

// ---------------------------------------------------------------------------
// fp16 mma.sync GEMM: K-step 32, 3-stage cp.async, ldmatrix fragments.
// CTA 128x128, 8 warps of 64x32. K=2048 -> 64 iterations, ONE barrier each.
// ---------------------------------------------------------------------------
template<bool HALF_OUT>
__device__ __forceinline__ void gemm128_h(
    const __half* __restrict__ A, const __half* __restrict__ Wt,
    void* __restrict__ C, int ldc, int row0, int wc0)
{
    extern __shared__ __align__(16) __half smh[];
    const uint32_t asb = smem_u32(smh);                 // [NSTG][128][40]
    const uint32_t bsb = asb + NSTG * ASTG32 * 2;       // [NSTG][128][40]

    const int tid = threadIdx.x;
    const int wid = tid >> 5, lane = tid & 31;
    const int g = lane >> 2, c = lane & 3;
    const int wm = (wid & 1) * 64;
    const int wn = (wid >> 1) * 32;
    const int l7 = lane & 7, lb = (lane >> 3) & 1, lh = lane >> 4;

    const int lrow = tid >> 1, seg = tid & 1;           // row, 32B-half select
    const __half* asrc = A  + (size_t)(row0 + lrow) * 2048 + seg * 16;
    const __half* bsrc = Wt + (size_t)(wc0 + lrow) * 2048 + seg * 16;
    const uint32_t adst = asb + (lrow * 40 + seg * 16) * 2;
    const uint32_t bdst = bsb + (lrow * 40 + seg * 16) * 2;

    float acc[4][4][4];
    #pragma unroll
    for (int mt = 0; mt < 4; mt++)
        #pragma unroll
        for (int nt = 0; nt < 4; nt++)
            #pragma unroll
            for (int e = 0; e < 4; e++) acc[mt][nt][e] = 0.f;

    // prologue: k-blocks 0,1 into stages 0,1
    #pragma unroll
    for (int s = 0; s < NSTG - 1; s++) {
        cpa16(adst + s * ASTG32 * 2,      asrc + s * 32);
        cpa16(adst + s * ASTG32 * 2 + 16, asrc + s * 32 + 8);
        cpa16(bdst + s * ASTG32 * 2,      bsrc + s * 32);
        cpa16(bdst + s * ASTG32 * 2 + 16, bsrc + s * 32 + 8);
        CP_COMMIT();
    }

    int buf = 0;
    for (int i = 0; i < 64; ++i) {
        CP_WAIT(1);
        __syncthreads();

        const uint32_t Ab = asb + buf * ASTG32 * 2;
        const uint32_t Bb = bsb + buf * ASTG32 * 2;
        #pragma unroll
        for (int kc = 0; kc < 2; kc++) {
            uint32_t af[4][4], bf[2][4];
            #pragma unroll
            for (int mt = 0; mt < 4; mt++)
                ldsm4(af[mt], Ab + ((wm + mt * 16 + l7 + lb * 8) * 40 + kc * 16 + lh * 8) * 2);
            #pragma unroll
            for (int ntp = 0; ntp < 2; ntp++)
                ldsm4(bf[ntp], Bb + ((wn + ntp * 16 + lh * 8 + l7) * 40 + kc * 16 + lb * 8) * 2);
            #pragma unroll
            for (int mt = 0; mt < 4; mt++) {
                #pragma unroll
                for (int ntp = 0; ntp < 2; ntp++) {
                    mma_f16(acc[mt][ntp * 2],     af[mt], &bf[ntp][0]);
                    mma_f16(acc[mt][ntp * 2 + 1], af[mt], &bf[ntp][2]);
                }
            }
        }

        int nk = i + NSTG - 1;
        if (nk < 64) {
            int s = buf + 2 >= NSTG ? buf + 2 - NSTG : buf + 2;
            cpa16(adst + s * ASTG32 * 2,      asrc + nk * 32);
            cpa16(adst + s * ASTG32 * 2 + 16, asrc + nk * 32 + 8);
            cpa16(bdst + s * ASTG32 * 2,      bsrc + nk * 32);
            cpa16(bdst + s * ASTG32 * 2 + 16, bsrc + nk * 32 + 8);
        }
        CP_COMMIT();
        buf = buf + 1 >= NSTG ? 0 : buf + 1;
    }

    #pragma unroll
    for (int mt = 0; mt < 4; mt++) {
        int r = row0 + wm + mt * 16 + g;
        #pragma unroll
        for (int nt = 0; nt < 4; nt++) {
            int col = wc0 + wn + nt * 8 + 2 * c;
            if (HALF_OUT) {
                __half* Ch = (__half*)C;
                *(uint32_t*)&Ch[(size_t)r * ldc + col] =
                    packh2(acc[mt][nt][0], acc[mt][nt][1]);
                *(uint32_t*)&Ch[(size_t)(r + 8) * ldc + col] =
                    packh2(acc[mt][nt][2], acc[mt][nt][3]);
            } else {
                float* Cf = (float*)C;
                *(float2*)&Cf[(size_t)r * ldc + col] =
                    make_float2(acc[mt][nt][0], acc[mt][nt][1]);
                *(float2*)&Cf[(size_t)(r + 8) * ldc + col] =
                    make_float2(acc[mt][nt][2], acc[mt][nt][3]);
            }
        }
    }
}

__global__ __launch_bounds__(256, 2) void qkv_gemm_h()
{
    int col0 = blockIdx.x * 128, row0 = blockIdx.y * 128;
    const __half* Wt; __half* C; int ldc, wc0;
    if (col0 < 2048)      { Wt = g_Wqh; C = g_qh; ldc = 2048; wc0 = col0; }
    else if (col0 < 2560) { Wt = g_Wkh; C = g_kh; ldc = 512;  wc0 = col0 - 2048; }
    else                  { Wt = g_Wvh; C = g_vh; ldc = 512;  wc0 = col0 - 2560; }
    gemm128_h<true>(g_xh, Wt, C, ldc, row0, wc0);
}

__global__ __launch_bounds__(256, 2) void out_gemm_h(float* __restrict__ out)
{
    int col0 = blockIdx.x * 128, row0 = blockIdx.y * 128;
    gemm128_h<false>(g_attnh, g_Woh, out, 2048, row0, col0);
}

// ---------------------------------------------------------------------------
// RoPE on half K buffer (Q rope fused into flash)
// ---------------------------------------------------------------------------
__global__ void rope_k_kernel(const float* __restrict__ cosb,
                              const float* __restrict__ sinb)
{
    int idx = blockIdx.x * blockDim.x + threadIdx.x;
    int total = B_ * S_ * KVH_ * 32;
    if (idx >= total) return;
    int d = idx & 31;
    int h = (idx >> 5) % KVH_;
    int s = (idx / (32 * KVH_)) % S_;
    int b = idx / (32 * KVH_ * S_);
    __half* row = g_kh + (((size_t)(b * S_ + s)) * KVH_ + h) * 64;
    float c1 = cosb[s * 64 + d],      s1 = sinb[s * 64 + d];
    float c2 = cosb[s * 64 + d + 32], s2 = sinb[s * 64 + d + 32];
    float x1 = __half2float(row[d]), x2 = __half2float(row[d + 32]);
    row[d]      = __float2half(x1 * c1 - x2 * s1);
    row[d + 32] = __float2half(x2 * c2 + x1 * s2);
}

// ---------------------------------------------------------------------------
// Flash attention fp16: 3-stage cp.async, one barrier/tile, ldmatrix,
// RoPE-Q fused, exp2-domain softmax (log2e folded into Q scale).
// ---------------------------------------------------------------------------
#define FSTG 9216   // bytes per stage per matrix: 64*72*2
#define QSCALE 0.180336880f   // 0.125 * log2(e)

__global__ __launch_bounds__(256, 2) void flash_h_kernel(
    const float* __restrict__ cosb, const float* __restrict__ sinb)
{
    extern __shared__ __align__(16) __half fsm[];
    const uint32_t skb = smem_u32(fsm);           // 3 K stages
    const uint32_t svb = skb + 3 * FSTG;          // 3 V stages

    const int tid = threadIdx.x;
    const int wid = tid >> 5, lane = tid & 31;
    const int g = lane >> 2, c = lane & 3;
    const int l7 = lane & 7, lb = (lane >> 3) & 1, lh = lane >> 4;
    const int qb = blockIdx.x, h = blockIdx.y, b = blockIdx.z;
    const int kvh = h >> 2;

    const __half* kvK = g_kh + ((size_t)(b * S_) * KVH_ + kvh) * 64;
    const __half* kvV = g_vh + ((size_t)(b * S_) * KVH_ + kvh) * 64;
    const int r0c = tid >> 3, c8 = tid & 7;

    // ---- Q fragments with fused RoPE + QSCALE (log2-domain) ----
    const __half* qr = g_qh + ((size_t)(b * S_ + qb * 128 + wid * 16) * H_ + h) * 64;
    const int s0 = qb * 128 + wid * 16 + g;
    uint32_t qa[4][4];
    #pragma unroll
    for (int kc = 0; kc < 4; kc++) {
        #pragma unroll
        for (int e = 0; e < 4; e++) {
            const int rr = (e & 1) ? (g + 8) : g;
            const int sidx = (e & 1) ? (s0 + 8) : s0;
            const int d = kc * 16 + 2 * c + ((e >> 1) ? 8 : 0);
            __half2 qv = *(const __half2*)&qr[(size_t)rr * 2048 + d];
            __half2 pv = *(const __half2*)&qr[(size_t)rr * 2048 + (d ^ 32)];
            float2 cs = *(const float2*)&cosb[sidx * 64 + d];
            float2 sn = *(const float2*)&sinb[sidx * 64 + d];
            float sgn = (d < 32) ? -1.f : 1.f;
            float r0v = (__half2float(qv.x) * cs.x + sgn * __half2float(pv.x) * sn.x) * QSCALE;
            float r1v = (__half2float(qv.y) * cs.y + sgn * __half2float(pv.y) * sn.y) * QSCALE;
            qa[kc][e] = packh2(r0v, r1v);
        }
    }

    float o[8][4];
    #pragma unroll
    for (int dt = 0; dt < 8; dt++)
        #pragma unroll
        for (int e = 0; e < 4; e++) o[dt][e] = 0.f;
    float m0 = -1.0e30f, m1 = -1.0e30f, l0 = 0.f, l1 = 0.f;

    // prologue: stages 0, 1
    #pragma unroll
    for (int s = 0; s < 2; s++) {
        const __half* kb = kvK + (size_t)s * 64 * 512;
        const __half* vb = kvV + (size_t)s * 64 * 512;
        #pragma unroll
        for (int u = 0; u < 2; u++) {
            int r = r0c + u * 32;
            cpa16(skb + s * FSTG + (r * 72 + c8 * 8) * 2, kb + (size_t)r * 512 + c8 * 8);
            cpa16(svb + s * FSTG + (r * 72 + c8 * 8) * 2, vb + (size_t)r * 512 + c8 * 8);
        }
        CP_COMMIT();
    }

    int stage = 0;
    for (int jt = 0; jt < 16; ++jt) {
        CP_WAIT(1);
        __syncthreads();

        const uint32_t Kb = skb + stage * FSTG;
        const uint32_t Vb = svb + stage * FSTG;

        // S (log2-domain) = Q @ K^T
        float s[8][4];
        #pragma unroll
        for (int nt = 0; nt < 8; nt++)
            #pragma unroll
            for (int e = 0; e < 4; e++) s[nt][e] = 0.f;
        #pragma unroll
        for (int nt = 0; nt < 8; nt++) {
            #pragma unroll
            for (int kc2 = 0; kc2 < 2; kc2++) {
                uint32_t bk[4];
                ldsm4(bk, Kb + ((nt * 8 + l7) * 72 + kc2 * 32 + (lane >> 3) * 8) * 2);
                mma_f16(s[nt], qa[kc2 * 2],     &bk[0]);
                mma_f16(s[nt], qa[kc2 * 2 + 1], &bk[2]);
            }
        }

        // online softmax in exp2 domain
        float tm0 = -1.0e30f, tm1 = -1.0e30f;
        #pragma unroll
        for (int nt = 0; nt < 8; nt++) {
            tm0 = fmaxf(tm0, fmaxf(s[nt][0], s[nt][1]));
            tm1 = fmaxf(tm1, fmaxf(s[nt][2], s[nt][3]));
        }
        tm0 = fmaxf(tm0, __shfl_xor_sync(0xffffffffu, tm0, 1));
        tm0 = fmaxf(tm0, __shfl_xor_sync(0xffffffffu, tm0, 2));
        tm1 = fmaxf(tm1, __shfl_xor_sync(0xffffffffu, tm1, 1));
        tm1 = fmaxf(tm1, __shfl_xor_sync(0xffffffffu, tm1, 2));

        float nm0 = fmaxf(m0, tm0), nm1 = fmaxf(m1, tm1);
        float al0 = exp2f(m0 - nm0), al1 = exp2f(m1 - nm1);
        m0 = nm0; m1 = nm1;

        uint32_t pk0[8], pk1[8];
        float sum0 = 0.f, sum1 = 0.f;
        #pragma unroll
        for (int nt = 0; nt < 8; nt++) {
            __half2 h0 = __floats2half2_rn(exp2f(s[nt][0] - nm0), exp2f(s[nt][1] - nm0));
            __half2 h1 = __floats2half2_rn(exp2f(s[nt][2] - nm1), exp2f(s[nt][3] - nm1));
            pk0[nt] = *(uint32_t*)&h0;
            pk1[nt] = *(uint32_t*)&h1;
            float2 r0 = __half22float2(h0), r1 = __half22float2(h1);
            sum0 += r0.x + r0.y;
            sum1 += r1.x + r1.y;
        }
        sum0 += __shfl_xor_sync(0xffffffffu, sum0, 1);
        sum0 += __shfl_xor_sync(0xffffffffu, sum0, 2);
        sum1 += __shfl_xor_sync(0xffffffffu, sum1, 1);
        sum1 += __shfl_xor_sync(0xffffffffu, sum1, 2);
        l0 = l0 * al0 + sum0;
        l1 = l1 * al1 + sum1;

        #pragma unroll
        for (int dt = 0; dt < 8; dt++) {
            o[dt][0] *= al0; o[dt][1] *= al0;
            o[dt][2] *= al1; o[dt][3] *= al1;
        }

        // O += P @ V
        #pragma unroll
        for (int kc = 0; kc < 4; kc++) {
            uint32_t a[4] = { pk0[2 * kc], pk1[2 * kc], pk0[2 * kc + 1], pk1[2 * kc + 1] };
            #pragma unroll
            for (int dtp = 0; dtp < 4; dtp++) {
                uint32_t bv[4];
                ldsm4t(bv, Vb + ((kc * 16 + lb * 8 + l7) * 72 + dtp * 16 + lh * 8) * 2);
                mma_f16(o[dtp * 2],     a, &bv[0]);
                mma_f16(o[dtp * 2 + 1], a, &bv[2]);
            }
        }

        // prefetch tile jt+2 into stage (stage+2)%3
        if (jt + 2 < 16) {
            const int ws = (stage + 2 >= 3) ? (stage + 2 - 3) : (stage + 2);
            const __half* kb = kvK + (size_t)(jt + 2) * 64 * 512;
            const __half* vb = kvV + (size_t)(jt + 2) * 64 * 512;
            #pragma unroll
            for (int u = 0; u < 2; u++) {
                int r = r0c + u * 32;
                cpa16(skb + ws * FSTG + (r * 72 + c8 * 8) * 2, kb + (size_t)r * 512 + c8 * 8);
                cpa16(svb + ws * FSTG + (r * 72 + c8 * 8) * 2, vb + (size_t)r * 512 + c8 * 8);
            }
        }
        CP_COMMIT();
        stage = (stage + 1 >= 3) ? 0 : stage + 1;
    }

    float inv0 = 1.f / l0, inv1 = 1.f / l1;
    __half* obase = g_attnh + ((size_t)(b * S_ + qb * 128 + wid * 16) * H_ + h) * 64;
    #pragma unroll
    for (int dt = 0; dt < 8; dt++) {
        *(uint32_t*)&obase[(size_t)g * 2048 + dt * 8 + 2 * c] =
            packh2(o[dt][0] * inv0, o[dt][1] * inv0);
        *(uint32_t*)&obase[(size_t)(g + 8) * 2048 + dt * 8 + 2 * c] =
            packh2(o[dt][2] * inv1, o[dt][3] * inv1);
    }
}

// ---------------------------------------------------------------------------
extern "C" void kernel_launch(void* const* d_in, const int* in_sizes, int n_in,
                              void* d_out, int out_size)
{
    (void)in_sizes; (void)n_in; (void)out_size;
    const float* x   = (const float*)d_in[0];
    const float* cb  = (const float*)d_in[1];
    const float* sb  = (const float*)d_in[2];
    const float* Wq  = (const float*)d_in[3];
    const float* Wk  = (const float*)d_in[4];
    const float* Wv  = (const float*)d_in[5];
    const float* Wo  = (const float*)d_in[6];
    float* out = (float*)d_out;

    const int GEMM_SMEM  = NSTG * ASTG32 * 2 * 2;    // 61440 B
    const int FLASH_SMEM = 6 * FSTG;                  // 55296 B
    cudaFuncSetAttribute(qkv_gemm_h, cudaFuncAttributeMaxDynamicSharedMemorySize, GEMM_SMEM);
    cudaFuncSetAttribute(out_gemm_h, cudaFuncAttributeMaxDynamicSharedMemorySize, GEMM_SMEM);
    cudaFuncSetAttribute(flash_h_kernel, cudaFuncAttributeMaxDynamicSharedMemorySize, FLASH_SMEM);

    __half* xh; __half* wqh; __half* wkh; __half* wvh; __half* woh;
    cudaGetSymbolAddress((void**)&xh,  g_xh);
    cudaGetSymbolAddress((void**)&wqh, g_Wqh);
    cudaGetSymbolAddress((void**)&wkh, g_Wkh);
    cudaGetSymbolAddress((void**)&wvh, g_Wvh);
    cudaGetSymbolAddress((void**)&woh, g_Woh);

    convh_kernel<<<(8388608 / 4 + 255) / 256, 256>>>(x, xh, 8388608 / 4);

    dim3 tb(32, 8);
    convT_all_kernel<<<dim3(64, 64, 4), tb>>>(Wq, Wk, Wv, Wo, wqh, wkh, wvh, woh);

    qkv_gemm_h<<<dim3(3072 / 128, 4096 / 128), 256, GEMM_SMEM>>>();

    rope_k_kernel<<<(B_ * S_ * KVH_ * 32 + 255) / 256, 256>>>(cb, sb);

    flash_h_kernel<<<dim3(S_ / 128, H_, B_), 256, FLASH_SMEM>>>(cb, sb);

    out_gemm_h<<<dim3(2048 / 128, 4096 / 128), 256, GEMM_SMEM>>>(out);
}

// round 12
// speedup vs baseline: 2.4930x; 1.0273x over previous
#include <cuda_runtime.h>
#include <cuda_fp16.h>
#include <cstdint>

#define B_   4
#define S_   1024
#define D_   2048
#define H_   32
#define KVH_ 8
#define HD_  64

// GEMM: K-step 32, 3 smem stages
#define NSTG   3
#define ASTG32 5120   // halves per stage per matrix: 128 * 40

// ---------------- device scratch ----------------
__device__ __half g_qh[B_ * S_ * H_ * HD_];   // raw Q (rope applied in flash)
__device__ __half g_kh[B_ * S_ * KVH_ * HD_]; // roped K
__device__ __half g_vh[B_ * S_ * KVH_ * HD_];
__device__ __half g_attnh[B_ * S_ * H_ * HD_];
__device__ __half g_xh[B_ * S_ * D_];
__device__ __half g_Wqh[2048 * 2048];   // transposed [N][K]
__device__ __half g_Wkh[512 * 2048];
__device__ __half g_Wvh[512 * 2048];
__device__ __half g_Woh[2048 * 2048];

__device__ __forceinline__ uint32_t smem_u32(const void* p) {
    uint32_t a;
    asm("{ .reg .u64 t; cvta.to.shared.u64 t, %1; cvt.u32.u64 %0, t; }"
        : "=r"(a) : "l"(p));
    return a;
}
__device__ __forceinline__ void cpa16(uint32_t dst, const void* src) {
    asm volatile("cp.async.cg.shared.global [%0], [%1], 16;" :: "r"(dst), "l"(src));
}
#define CP_COMMIT() asm volatile("cp.async.commit_group;" ::: "memory")
#define CP_WAIT(n)  asm volatile("cp.async.wait_group %0;" :: "n"(n) : "memory")

__device__ __forceinline__ uint32_t packh2(float a, float b) {
    __half2 h = __floats2half2_rn(a, b);
    return *(uint32_t*)&h;
}
__device__ __forceinline__ uint32_t ex2_h2(float a, float b) {
    // pack (a,b) to half2, packed MUFU ex2
    __half2 e = __floats2half2_rn(a, b);
    uint32_t u = *(uint32_t*)&e, r;
    asm("ex2.approx.f16x2 %0, %1;" : "=r"(r) : "r"(u));
    return r;
}
__device__ __forceinline__ void mma_f16(float* d, const uint32_t* a, const uint32_t* b) {
    asm volatile(
        "mma.sync.aligned.m16n8k16.row.col.f32.f16.f16.f32 "
        "{%0,%1,%2,%3}, {%4,%5,%6,%7}, {%8,%9}, {%0,%1,%2,%3};"
        : "+f"(d[0]), "+f"(d[1]), "+f"(d[2]), "+f"(d[3])
        : "r"(a[0]), "r"(a[1]), "r"(a[2]), "r"(a[3]), "r"(b[0]), "r"(b[1]));
}
__device__ __forceinline__ void ldsm4(uint32_t* r, uint32_t addr) {
    asm volatile("ldmatrix.sync.aligned.m8n8.x4.shared.b16 {%0,%1,%2,%3}, [%4];"
        : "=r"(r[0]), "=r"(r[1]), "=r"(r[2]), "=r"(r[3]) : "r"(addr));
}
__device__ __forceinline__ void ldsm4t(uint32_t* r, uint32_t addr) {
    asm volatile("ldmatrix.sync.aligned.m8n8.x4.trans.shared.b16 {%0,%1,%2,%3}, [%4];"
        : "=r"(r[0]), "=r"(r[1]), "=r"(r[2]), "=r"(r[3]) : "r"(addr));
}

// ---------------------------------------------------------------------------
// Merged prep: z<4 -> weight transpose+f16; z==4 -> x f32->f16 copy
// ---------------------------------------------------------------------------
__global__ void prep_kernel(const float* __restrict__ x,
                            const float* __restrict__ Wq, const float* __restrict__ Wk,
                            const float* __restrict__ Wv, const float* __restrict__ Wo,
                            __half* __restrict__ xh,
                            __half* __restrict__ dq, __half* __restrict__ dk,
                            __half* __restrict__ dv, __half* __restrict__ dob)
{
    const int z = blockIdx.z;
    const int tx = threadIdx.x, ty = threadIdx.y;   // 32 x 8

    if (z == 4) {
        // x conversion: 8.4M floats = 2,097,152 float4s; 4096 blocks x 256 thr x 2
        int bid = blockIdx.y * 64 + blockIdx.x;
        int i = bid * 256 + ty * 32 + tx;
        #pragma unroll
        for (int u = 0; u < 2; u++) {
            int idx = i + u * 1048576;
            float4 v = *(const float4*)(x + (size_t)idx * 4);
            uint2 o;
            o.x = packh2(v.x, v.y);
            o.y = packh2(v.z, v.w);
            *(uint2*)(xh + (size_t)idx * 4) = o;
        }
        return;
    }

    const float* src; __half* dst; int cols;
    if (z == 0)      { src = Wq; dst = dq;  cols = 2048; }
    else if (z == 1) { src = Wk; dst = dk;  cols = 512;  }
    else if (z == 2) { src = Wv; dst = dv;  cols = 512;  }
    else             { src = Wo; dst = dob; cols = 2048; }
    int bx = blockIdx.x * 32, by = blockIdx.y * 32;
    if (bx >= cols) return;

    __shared__ float t[32][33];
    #pragma unroll
    for (int j = 0; j < 32; j += 8)
        t[ty + j][tx] = src[(size_t)(by + ty + j) * cols + bx + tx];
    __syncthreads();
    #pragma unroll
    for (int j = 0; j < 32; j += 8)
        dst[(size_t)(bx + ty + j) * 2048 + by + tx] = __float2half(t[tx][ty + j]);
}

// ---------------------------------------------------------------------------
// fp16 mma.sync GEMM: K-step 32, 3-stage cp.async, ldmatrix. (unchanged R11)
// ---------------------------------------------------------------------------
template<bool HALF_OUT>
__device__ __forceinline__ void gemm128_h(
    const __half* __restrict__ A, const __half* __restrict__ Wt,
    void* __restrict__ C, int ldc, int row0, int wc0)
{
    extern __shared__ __align__(16) __half smh[];
    const uint32_t asb = smem_u32(smh);
    const uint32_t bsb = asb + NSTG * ASTG32 * 2;

    const int tid = threadIdx.x;
    const int wid = tid >> 5, lane = tid & 31;
    const int g = lane >> 2, c = lane & 3;
    const int wm = (wid & 1) * 64;
    const int wn = (wid >> 1) * 32;
    const int l7 = lane & 7, lb = (lane >> 3) & 1, lh = lane >> 4;

    const int lrow = tid >> 1, seg = tid & 1;
    const __half* asrc = A  + (size_t)(row0 + lrow) * 2048 + seg * 16;
    const __half* bsrc = Wt + (size_t)(wc0 + lrow) * 2048 + seg * 16;
    const uint32_t adst = asb + (lrow * 40 + seg * 16) * 2;
    const uint32_t bdst = bsb + (lrow * 40 + seg * 16) * 2;

    float acc[4][4][4];
    #pragma unroll
    for (int mt = 0; mt < 4; mt++)
        #pragma unroll
        for (int nt = 0; nt < 4; nt++)
            #pragma unroll
            for (int e = 0; e < 4; e++) acc[mt][nt][e] = 0.f;

    #pragma unroll
    for (int s = 0; s < NSTG - 1; s++) {
        cpa16(adst + s * ASTG32 * 2,      asrc + s * 32);
        cpa16(adst + s * ASTG32 * 2 + 16, asrc + s * 32 + 8);
        cpa16(bdst + s * ASTG32 * 2,      bsrc + s * 32);
        cpa16(bdst + s * ASTG32 * 2 + 16, bsrc + s * 32 + 8);
        CP_COMMIT();
    }

    int buf = 0;
    for (int i = 0; i < 64; ++i) {
        CP_WAIT(1);
        __syncthreads();

        const uint32_t Ab = asb + buf * ASTG32 * 2;
        const uint32_t Bb = bsb + buf * ASTG32 * 2;
        #pragma unroll
        for (int kc = 0; kc < 2; kc++) {
            uint32_t af[4][4], bf[2][4];
            #pragma unroll
            for (int mt = 0; mt < 4; mt++)
                ldsm4(af[mt], Ab + ((wm + mt * 16 + l7 + lb * 8) * 40 + kc * 16 + lh * 8) * 2);
            #pragma unroll
            for (int ntp = 0; ntp < 2; ntp++)
                ldsm4(bf[ntp], Bb + ((wn + ntp * 16 + lh * 8 + l7) * 40 + kc * 16 + lb * 8) * 2);
            #pragma unroll
            for (int mt = 0; mt < 4; mt++) {
                #pragma unroll
                for (int ntp = 0; ntp < 2; ntp++) {
                    mma_f16(acc[mt][ntp * 2],     af[mt], &bf[ntp][0]);
                    mma_f16(acc[mt][ntp * 2 + 1], af[mt], &bf[ntp][2]);
                }
            }
        }

        int nk = i + NSTG - 1;
        if (nk < 64) {
            int s = buf + 2 >= NSTG ? buf + 2 - NSTG : buf + 2;
            cpa16(adst + s * ASTG32 * 2,      asrc + nk * 32);
            cpa16(adst + s * ASTG32 * 2 + 16, asrc + nk * 32 + 8);
            cpa16(bdst + s * ASTG32 * 2,      bsrc + nk * 32);
            cpa16(bdst + s * ASTG32 * 2 + 16, bsrc + nk * 32 + 8);
        }
        CP_COMMIT();
        buf = buf + 1 >= NSTG ? 0 : buf + 1;
    }

    #pragma unroll
    for (int mt = 0; mt < 4; mt++) {
        int r = row0 + wm + mt * 16 + g;
        #pragma unroll
        for (int nt = 0; nt < 4; nt++) {
            int col = wc0 + wn + nt * 8 + 2 * c;
            if (HALF_OUT) {
                __half* Ch = (__half*)C;
                *(uint32_t*)&Ch[(size_t)r * ldc + col] =
                    packh2(acc[mt][nt][0], acc[mt][nt][1]);
                *(uint32_t*)&Ch[(size_t)(r + 8) * ldc + col] =
                    packh2(acc[mt][nt][2], acc[mt][nt][3]);
            } else {
                float* Cf = (float*)C;
                *(float2*)&Cf[(size_t)r * ldc + col] =
                    make_float2(acc[mt][nt][0], acc[mt][nt][1]);
                *(float2*)&Cf[(size_t)(r + 8) * ldc + col] =
                    make_float2(acc[mt][nt][2], acc[mt][nt][3]);
            }
        }
    }
}

__global__ __launch_bounds__(256, 2) void qkv_gemm_h()
{
    int col0 = blockIdx.x * 128, row0 = blockIdx.y * 128;
    const __half* Wt; __half* C; int ldc, wc0;
    if (col0 < 2048)      { Wt = g_Wqh; C = g_qh; ldc = 2048; wc0 = col0; }
    else if (col0 < 2560) { Wt = g_Wkh; C = g_kh; ldc = 512;  wc0 = col0 - 2048; }
    else                  { Wt = g_Wvh; C = g_vh; ldc = 512;  wc0 = col0 - 2560; }
    gemm128_h<true>(g_xh, Wt, C, ldc, row0, wc0);
}

__global__ __launch_bounds__(256, 2) void out_gemm_h(float* __restrict__ out)
{
    int col0 = blockIdx.x * 128, row0 = blockIdx.y * 128;
    gemm128_h<false>(g_attnh, g_Woh, out, 2048, row0, col0);
}

// ---------------------------------------------------------------------------
// RoPE on half K buffer (Q rope fused into flash)
// ---------------------------------------------------------------------------
__global__ void rope_k_kernel(const float* __restrict__ cosb,
                              const float* __restrict__ sinb)
{
    int idx = blockIdx.x * blockDim.x + threadIdx.x;
    int total = B_ * S_ * KVH_ * 32;
    if (idx >= total) return;
    int d = idx & 31;
    int h = (idx >> 5) % KVH_;
    int s = (idx / (32 * KVH_)) % S_;
    int b = idx / (32 * KVH_ * S_);
    __half* row = g_kh + (((size_t)(b * S_ + s)) * KVH_ + h) * 64;
    float c1 = cosb[s * 64 + d],      s1 = sinb[s * 64 + d];
    float c2 = cosb[s * 64 + d + 32], s2 = sinb[s * 64 + d + 32];
    float x1 = __half2float(row[d]), x2 = __half2float(row[d + 32]);
    row[d]      = __float2half(x1 * c1 - x2 * s1);
    row[d + 32] = __float2half(x2 * c2 + x1 * s2);
}

// ---------------------------------------------------------------------------
// Flash attention fp16: 3-stage cp.async, one barrier/tile, ldmatrix,
// RoPE-Q fused, exp2-domain softmax via packed ex2.approx.f16x2.
// ---------------------------------------------------------------------------
#define FSTG 9216   // bytes per stage per matrix: 64*72*2
#define QSCALE 0.180336880f   // 0.125 * log2(e)

__global__ __launch_bounds__(256, 2) void flash_h_kernel(
    const float* __restrict__ cosb, const float* __restrict__ sinb)
{
    extern __shared__ __align__(16) __half fsm[];
    const uint32_t skb = smem_u32(fsm);           // 3 K stages
    const uint32_t svb = skb + 3 * FSTG;          // 3 V stages

    const int tid = threadIdx.x;
    const int wid = tid >> 5, lane = tid & 31;
    const int g = lane >> 2, c = lane & 3;
    const int l7 = lane & 7, lb = (lane >> 3) & 1, lh = lane >> 4;
    const int qb = blockIdx.x, h = blockIdx.y, b = blockIdx.z;
    const int kvh = h >> 2;

    const __half* kvK = g_kh + ((size_t)(b * S_) * KVH_ + kvh) * 64;
    const __half* kvV = g_vh + ((size_t)(b * S_) * KVH_ + kvh) * 64;
    const int r0c = tid >> 3, c8 = tid & 7;

    // ---- Q fragments with fused RoPE + QSCALE (log2-domain) ----
    const __half* qr = g_qh + ((size_t)(b * S_ + qb * 128 + wid * 16) * H_ + h) * 64;
    const int s0 = qb * 128 + wid * 16 + g;
    uint32_t qa[4][4];
    #pragma unroll
    for (int kc = 0; kc < 4; kc++) {
        #pragma unroll
        for (int e = 0; e < 4; e++) {
            const int rr = (e & 1) ? (g + 8) : g;
            const int sidx = (e & 1) ? (s0 + 8) : s0;
            const int d = kc * 16 + 2 * c + ((e >> 1) ? 8 : 0);
            __half2 qv = *(const __half2*)&qr[(size_t)rr * 2048 + d];
            __half2 pv = *(const __half2*)&qr[(size_t)rr * 2048 + (d ^ 32)];
            float2 cs = *(const float2*)&cosb[sidx * 64 + d];
            float2 sn = *(const float2*)&sinb[sidx * 64 + d];
            float sgn = (d < 32) ? -1.f : 1.f;
            float r0v = (__half2float(qv.x) * cs.x + sgn * __half2float(pv.x) * sn.x) * QSCALE;
            float r1v = (__half2float(qv.y) * cs.y + sgn * __half2float(pv.y) * sn.y) * QSCALE;
            qa[kc][e] = packh2(r0v, r1v);
        }
    }

    float o[8][4];
    #pragma unroll
    for (int dt = 0; dt < 8; dt++)
        #pragma unroll
        for (int e = 0; e < 4; e++) o[dt][e] = 0.f;
    float m0 = -1.0e30f, m1 = -1.0e30f, l0 = 0.f, l1 = 0.f;

    // prologue: stages 0, 1
    #pragma unroll
    for (int s = 0; s < 2; s++) {
        const __half* kb = kvK + (size_t)s * 64 * 512;
        const __half* vb = kvV + (size_t)s * 64 * 512;
        #pragma unroll
        for (int u = 0; u < 2; u++) {
            int r = r0c + u * 32;
            cpa16(skb + s * FSTG + (r * 72 + c8 * 8) * 2, kb + (size_t)r * 512 + c8 * 8);
            cpa16(svb + s * FSTG + (r * 72 + c8 * 8) * 2, vb + (size_t)r * 512 + c8 * 8);
        }
        CP_COMMIT();
    }

    int stage = 0;
    for (int jt = 0; jt < 16; ++jt) {
        CP_WAIT(1);
        __syncthreads();

        const uint32_t Kb = skb + stage * FSTG;
        const uint32_t Vb = svb + stage * FSTG;

        // S (log2-domain) = Q @ K^T
        float s[8][4];
        #pragma unroll
        for (int nt = 0; nt < 8; nt++)
            #pragma unroll
            for (int e = 0; e < 4; e++) s[nt][e] = 0.f;
        #pragma unroll
        for (int nt = 0; nt < 8; nt++) {
            #pragma unroll
            for (int kc2 = 0; kc2 < 2; kc2++) {
                uint32_t bk[4];
                ldsm4(bk, Kb + ((nt * 8 + l7) * 72 + kc2 * 32 + (lane >> 3) * 8) * 2);
                mma_f16(s[nt], qa[kc2 * 2],     &bk[0]);
                mma_f16(s[nt], qa[kc2 * 2 + 1], &bk[2]);
            }
        }

        // online softmax in exp2 domain
        float tm0 = -1.0e30f, tm1 = -1.0e30f;
        #pragma unroll
        for (int nt = 0; nt < 8; nt++) {
            tm0 = fmaxf(tm0, fmaxf(s[nt][0], s[nt][1]));
            tm1 = fmaxf(tm1, fmaxf(s[nt][2], s[nt][3]));
        }
        tm0 = fmaxf(tm0, __shfl_xor_sync(0xffffffffu, tm0, 1));
        tm0 = fmaxf(tm0, __shfl_xor_sync(0xffffffffu, tm0, 2));
        tm1 = fmaxf(tm1, __shfl_xor_sync(0xffffffffu, tm1, 1));
        tm1 = fmaxf(tm1, __shfl_xor_sync(0xffffffffu, tm1, 2));

        float nm0 = fmaxf(m0, tm0), nm1 = fmaxf(m1, tm1);
        float al0 = exp2f(m0 - nm0), al1 = exp2f(m1 - nm1);
        m0 = nm0; m1 = nm1;

        // P = exp2(S - m) via packed half MUFU; sums in f32
        uint32_t pk0[8], pk1[8];
        float sum0 = 0.f, sum1 = 0.f;
        #pragma unroll
        for (int nt = 0; nt < 8; nt++) {
            pk0[nt] = ex2_h2(s[nt][0] - nm0, s[nt][1] - nm0);
            pk1[nt] = ex2_h2(s[nt][2] - nm1, s[nt][3] - nm1);
            float2 f0 = __half22float2(*(__half2*)&pk0[nt]);
            float2 f1 = __half22float2(*(__half2*)&pk1[nt]);
            sum0 += f0.x + f0.y;
            sum1 += f1.x + f1.y;
        }
        sum0 += __shfl_xor_sync(0xffffffffu, sum0, 1);
        sum0 += __shfl_xor_sync(0xffffffffu, sum0, 2);
        sum1 += __shfl_xor_sync(0xffffffffu, sum1, 1);
        sum1 += __shfl_xor_sync(0xffffffffu, sum1, 2);
        l0 = l0 * al0 + sum0;
        l1 = l1 * al1 + sum1;

        #pragma unroll
        for (int dt = 0; dt < 8; dt++) {
            o[dt][0] *= al0; o[dt][1] *= al0;
            o[dt][2] *= al1; o[dt][3] *= al1;
        }

        // O += P @ V
        #pragma unroll
        for (int kc = 0; kc < 4; kc++) {
            uint32_t a[4] = { pk0[2 * kc], pk1[2 * kc], pk0[2 * kc + 1], pk1[2 * kc + 1] };
            #pragma unroll
            for (int dtp = 0; dtp < 4; dtp++) {
                uint32_t bv[4];
                ldsm4t(bv, Vb + ((kc * 16 + lb * 8 + l7) * 72 + dtp * 16 + lh * 8) * 2);
                mma_f16(o[dtp * 2],     a, &bv[0]);
                mma_f16(o[dtp * 2 + 1], a, &bv[2]);
            }
        }

        // prefetch tile jt+2 into stage (stage+2)%3
        if (jt + 2 < 16) {
            const int ws = (stage + 2 >= 3) ? (stage + 2 - 3) : (stage + 2);
            const __half* kb = kvK + (size_t)(jt + 2) * 64 * 512;
            const __half* vb = kvV + (size_t)(jt + 2) * 64 * 512;
            #pragma unroll
            for (int u = 0; u < 2; u++) {
                int r = r0c + u * 32;
                cpa16(skb + ws * FSTG + (r * 72 + c8 * 8) * 2, kb + (size_t)r * 512 + c8 * 8);
                cpa16(svb + ws * FSTG + (r * 72 + c8 * 8) * 2, vb + (size_t)r * 512 + c8 * 8);
            }
        }
        CP_COMMIT();
        stage = (stage + 1 >= 3) ? 0 : stage + 1;
    }

    float inv0 = 1.f / l0, inv1 = 1.f / l1;
    __half* obase = g_attnh + ((size_t)(b * S_ + qb * 128 + wid * 16) * H_ + h) * 64;
    #pragma unroll
    for (int dt = 0; dt < 8; dt++) {
        *(uint32_t*)&obase[(size_t)g * 2048 + dt * 8 + 2 * c] =
            packh2(o[dt][0] * inv0, o[dt][1] * inv0);
        *(uint32_t*)&obase[(size_t)(g + 8) * 2048 + dt * 8 + 2 * c] =
            packh2(o[dt][2] * inv1, o[dt][3] * inv1);
    }
}

// ---------------------------------------------------------------------------
extern "C" void kernel_launch(void* const* d_in, const int* in_sizes, int n_in,
                              void* d_out, int out_size)
{
    (void)in_sizes; (void)n_in; (void)out_size;
    const float* x   = (const float*)d_in[0];
    const float* cb  = (const float*)d_in[1];
    const float* sb  = (const float*)d_in[2];
    const float* Wq  = (const float*)d_in[3];
    const float* Wk  = (const float*)d_in[4];
    const float* Wv  = (const float*)d_in[5];
    const float* Wo  = (const float*)d_in[6];
    float* out = (float*)d_out;

    const int GEMM_SMEM  = NSTG * ASTG32 * 2 * 2;    // 61440 B
    const int FLASH_SMEM = 6 * FSTG;                  // 55296 B
    cudaFuncSetAttribute(qkv_gemm_h, cudaFuncAttributeMaxDynamicSharedMemorySize, GEMM_SMEM);
    cudaFuncSetAttribute(out_gemm_h, cudaFuncAttributeMaxDynamicSharedMemorySize, GEMM_SMEM);
    cudaFuncSetAttribute(flash_h_kernel, cudaFuncAttributeMaxDynamicSharedMemorySize, FLASH_SMEM);

    __half* xh; __half* wqh; __half* wkh; __half* wvh; __half* woh;
    cudaGetSymbolAddress((void**)&xh,  g_xh);
    cudaGetSymbolAddress((void**)&wqh, g_Wqh);
    cudaGetSymbolAddress((void**)&wkh, g_Wkh);
    cudaGetSymbolAddress((void**)&wvh, g_Wvh);
    cudaGetSymbolAddress((void**)&woh, g_Woh);

    dim3 tb(32, 8);
    prep_kernel<<<dim3(64, 64, 5), tb>>>(x, Wq, Wk, Wv, Wo, xh, wqh, wkh, wvh, woh);

    qkv_gemm_h<<<dim3(3072 / 128, 4096 / 128), 256, GEMM_SMEM>>>();

    rope_k_kernel<<<(B_ * S_ * KVH_ * 32 + 255) / 256, 256>>>(cb, sb);

    flash_h_kernel<<<dim3(S_ / 128, H_, B_), 256, FLASH_SMEM>>>(cb, sb);

    out_gemm_h<<<dim3(2048 / 128, 4096 / 128), 256, GEMM_SMEM>>>(out);
}